// round 13
// baseline (speedup 1.0000x reference)
#include <cuda_runtime.h>
#include <cuda_bf16.h>
#include <math.h>
#include <stdint.h>

// ---------------- problem constants ----------------
#define N_NODES   16384
#define N_EDGES   262144
#define NHID      128
#define NLAYERS   3
#define NBATCH    16
#define NSAMPLES  1024
#define DIMX      4
#define EPSV      1e-5f

#define WT_LAYER_STRIDE 393216
#define WT_W1A 0
#define WT_W1B 65536
#define WT_W2  131072
#define WT_U1  196608
#define WT_U2  327680

#define PDPS_SMEM  197632   // 1K pad + A 64K + W1a/W1b hi/lo 128K
#define EDGE_SMEM  132096   // 1K pad + A 64K + W 64K (single buffer now)
#define U1_SMEM    132096   // 1K pad + A 64K + W 64K

// ---------------- device scratch ----------------
__device__ float g_h [N_NODES * NHID];
__device__ float g_Pd[N_NODES * NHID];
__device__ float g_Ps[N_NODES * NHID];
__device__ float g_agg [N_NODES * NHID];
__device__ float g_agg2[N_NODES * NHID];
__device__ float g_t2[N_NODES * NHID];
__device__ float g_x [N_NODES * DIMX];
__device__ float g_naccA[2 * NBATCH * NHID];
__device__ float g_naccB[2 * NBATCH * NHID];
__device__ float g_dsum[32];
__device__ char  g_wt[NLAYERS * WT_LAYER_STRIDE];

// ---------------- helpers ----------------
__device__ __forceinline__ uint32_t smem_u32(const void* p) {
    uint32_t a;
    asm("{ .reg .u64 t; cvta.to.shared.u64 t, %1; cvt.u32.u64 %0, t; }" : "=r"(a) : "l"(p));
    return a;
}
__device__ __forceinline__ void red_add_v2(float* p, float a, float b) {
    asm volatile("red.global.add.v2.f32 [%0], {%1,%2};"
                 :: "l"(p), "f"(a), "f"(b) : "memory");
}
__device__ __forceinline__ uint32_t pack2(__nv_bfloat16 a, __nv_bfloat16 b) {
    return (uint32_t)__bfloat16_as_ushort(a) | ((uint32_t)__bfloat16_as_ushort(b) << 16);
}
__device__ __forceinline__ void ldmx4(uint32_t* r, uint32_t addr) {
    asm volatile("ldmatrix.sync.aligned.m8n8.x4.shared.b16 {%0,%1,%2,%3}, [%4];"
                 : "=r"(r[0]), "=r"(r[1]), "=r"(r[2]), "=r"(r[3]) : "r"(addr));
}
__device__ __forceinline__ void mma16816(float* c, const uint32_t* a, const uint32_t* b) {
    asm volatile("mma.sync.aligned.m16n8k16.row.col.f32.bf16.bf16.f32 "
                 "{%0,%1,%2,%3}, {%4,%5,%6,%7}, {%8,%9}, {%0,%1,%2,%3};"
                 : "+f"(c[0]), "+f"(c[1]), "+f"(c[2]), "+f"(c[3])
                 : "r"(a[0]), "r"(a[1]), "r"(a[2]), "r"(a[3]), "r"(b[0]), "r"(b[1]));
}

__device__ __forceinline__ void split4(float4 v, uint2& hv, uint2& lv) {
    __nv_bfloat16 h0 = __float2bfloat16(v.x);
    __nv_bfloat16 h1 = __float2bfloat16(v.y);
    __nv_bfloat16 h2 = __float2bfloat16(v.z);
    __nv_bfloat16 h3 = __float2bfloat16(v.w);
    __nv_bfloat16 l0 = __float2bfloat16(v.x - __bfloat162float(h0));
    __nv_bfloat16 l1 = __float2bfloat16(v.y - __bfloat162float(h1));
    __nv_bfloat16 l2 = __float2bfloat16(v.z - __bfloat162float(h2));
    __nv_bfloat16 l3 = __float2bfloat16(v.w - __bfloat162float(h3));
    hv = make_uint2(pack2(h0, h1), pack2(h2, h3));
    lv = make_uint2(pack2(l0, l1), pack2(l2, l3));
}
__device__ __forceinline__ void split2(float a, float b, uint32_t& hv, uint32_t& lv) {
    __nv_bfloat16 h0 = __float2bfloat16(a);
    __nv_bfloat16 h1 = __float2bfloat16(b);
    __nv_bfloat16 l0 = __float2bfloat16(a - __bfloat162float(h0));
    __nv_bfloat16 l1 = __float2bfloat16(b - __bfloat162float(h1));
    hv = pack2(h0, h1);
    lv = pack2(l0, l1);
}

__device__ __forceinline__ void compute_stats(const float* __restrict__ acc,
                                              int batch, float* s_stats, int tid) {
    if (tid < 128) {
        float s = acc[batch * 128 + tid];
        float q = acc[NBATCH * NHID + batch * 128 + tid];
        float mean = s * (1.0f / NSAMPLES);
        float var = q * (1.0f / NSAMPLES) - mean * mean;
        s_stats[tid] = mean;
        s_stats[128 + tid] = rsqrtf(var + EPSV);
    }
}

// ---------------- weight prep ----------------
struct PrepJobs {
    const float* src[15];
    char* dst[15];
    int nelem[15];
};
__global__ void prep_w_all(PrepJobs jobs) {
    int m = blockIdx.y;
    int idx = blockIdx.x * 256 + threadIdx.x;
    if (idx >= jobs.nelem[m]) return;
    const float* W = jobs.src[m];
    char* out = jobs.dst[m];
    int k = idx >> 7, n = idx & 127;
    float w = W[idx];
    __nv_bfloat16 hi = __float2bfloat16(w);
    __nv_bfloat16 lo = __float2bfloat16(w - __bfloat162float(hi));
    int phase = k >> 7, kk = k & 127;
    uint32_t off = (uint32_t)(n * 256 + ((((kk >> 3) ^ (n & 7)) << 4) | ((kk & 7) << 1)));
    *(__nv_bfloat16*)(out + (size_t)phase * 65536 + off) = hi;
    *(__nv_bfloat16*)(out + (size_t)phase * 65536 + 32768 + off) = lo;
}

// ---------------- encoder ----------------
__global__ void encoder_kernel(const float* __restrict__ X,
                               const float* __restrict__ W,
                               const float* __restrict__ B,
                               float* __restrict__ H) {
    int idx = blockIdx.x * blockDim.x + threadIdx.x;
    int n = idx >> 7;
    int c = idx & 127;
    float4 xv = ((const float4*)X)[n];
    float v = B[c];
    v += xv.x * W[c];
    v += xv.y * W[128 + c];
    v += xv.z * W[256 + c];
    v += xv.w * W[384 + c];
    H[idx] = v;
    g_agg[idx] = 0.f;
    if (idx < 2 * NBATCH * NHID) { g_naccA[idx] = 0.f; g_naccB[idx] = 0.f; }
    if (idx < 32) g_dsum[idx] = 0.f;
}

// ---------------- coalesced staging ----------------
template<int NTHREADS, int NROWS, int NORM>
__device__ __forceinline__ void stage_rows(
    const float* __restrict__ Abase, int row0,
    char* __restrict__ Ahi, char* __restrict__ Alo,
    const float* __restrict__ stats, int tid)
{
    const int sr  = tid >> 3;
    const int ch8 = tid & 7;
    const int ROWS_PER_PASS = NTHREADS / 8;
    const int NPASS = NROWS / ROWS_PER_PASS;
#pragma unroll
    for (int pass = 0; pass < NPASS; ++pass) {
        const int r = sr + pass * ROWS_PER_PASS;
        const int node = row0 + r;
        const float* arow = Abase + (size_t)node * 128;
        const int r7 = r & 7;
        const uint32_t r256 = (uint32_t)r * 256;
#pragma unroll
        for (int j = 0; j < 4; ++j) {
            const int c4 = (ch8 + j * 8) * 4;
            float4 v = *(const float4*)(arow + c4);
            if (NORM) {
                float4 m  = *(const float4*)(stats + c4);
                float4 iv = *(const float4*)(stats + 128 + c4);
                v.x = (v.x - m.x) * iv.x;
                v.y = (v.y - m.y) * iv.y;
                v.z = (v.z - m.z) * iv.z;
                v.w = (v.w - m.w) * iv.w;
            }
            uint2 hv, lv;
            split4(v, hv, lv);
            uint32_t off = r256 + ((((c4 >> 3) ^ r7) << 4) | ((c4 & 7) << 1));
            *(uint2*)(Ahi + off) = hv;
            *(uint2*)(Alo + off) = lv;
        }
    }
}

// ---------------- PdPs ----------------
template<int NORM>
__global__ __launch_bounds__(512, 1)
void tc_pdps(const float* __restrict__ A0, const char* __restrict__ Wt,
             float* __restrict__ Pd, float* __restrict__ Ps,
             const float* __restrict__ accPrev) {
    extern __shared__ char dyn[];
    __shared__ float s_stats[256];
    const int tid = threadIdx.x;
    const int wid = tid >> 5;
    const int lid = tid & 31;
    const int m0  = blockIdx.x * 128;
    uint32_t dyn_u32 = smem_u32(dyn);
    uint32_t pad = ((dyn_u32 + 1023u) & ~1023u) - dyn_u32;
    char* tiles = dyn + pad;
    uint32_t tiles_u32 = dyn_u32 + pad;

    if (NORM) {
        compute_stats(accPrev, m0 >> 10, s_stats, tid);
        __syncthreads();
    }
    stage_rows<512, 128, NORM>(A0, m0, tiles, tiles + 32768, s_stats, tid);
    {
        const float4* wsrc = (const float4*)Wt;
        float4* wdst = (float4*)(tiles + 65536);
#pragma unroll
        for (int j = 0; j < 16; ++j)
            wdst[tid + j * 512] = wsrc[tid + j * 512];
    }
    __syncthreads();

    const int warp_m = wid & 3;
    const int warp_n = wid >> 2;
    const int quad = lid >> 3;
    const int lrow = lid & 7;
    const int a_rl = (quad & 1) * 8 + lrow;
    const int akq  = quad >> 1;
    const int b_rl = (quad >> 1) * 8 + lrow;
    const int bkq  = quad & 1;
    uint32_t arow256[2]; int ar7[2];
#pragma unroll
    for (int mt = 0; mt < 2; ++mt) {
        int rr = warp_m * 32 + mt * 16 + a_rl;
        arow256[mt] = (uint32_t)rr * 256; ar7[mt] = rr & 7;
    }
    uint32_t brow256[2]; int br7[2];
#pragma unroll
    for (int pj = 0; pj < 2; ++pj) {
        int rr = warp_n * 32 + pj * 16 + b_rl;
        brow256[pj] = (uint32_t)rr * 256; br7[pj] = rr & 7;
    }
    const int gr = lid >> 2;
    const int gc = (lid & 3) << 1;

#pragma unroll
    for (int h2 = 0; h2 < 2; ++h2) {
        const uint32_t wb = tiles_u32 + 65536 + (uint32_t)h2 * 65536;
        float c[2][4][4];
#pragma unroll
        for (int mt = 0; mt < 2; ++mt)
#pragma unroll
            for (int nt = 0; nt < 4; ++nt)
#pragma unroll
                for (int i = 0; i < 4; ++i) c[mt][nt][i] = 0.f;

#pragma unroll
        for (int ks = 0; ks < 8; ++ks) {
            const int kb = ks * 2;
            uint32_t ahi[2][4], alo[2][4], bhi[2][4], blo[2][4];
#pragma unroll
            for (int mt = 0; mt < 2; ++mt) {
                uint32_t sw = (uint32_t)(((kb + akq) ^ ar7[mt]) << 4);
                ldmx4(ahi[mt], tiles_u32 + arow256[mt] + sw);
                ldmx4(alo[mt], tiles_u32 + 32768 + arow256[mt] + sw);
            }
#pragma unroll
            for (int pj = 0; pj < 2; ++pj) {
                uint32_t swb = (uint32_t)(((kb + bkq) ^ br7[pj]) << 4);
                ldmx4(bhi[pj], wb + brow256[pj] + swb);
                ldmx4(blo[pj], wb + 32768 + brow256[pj] + swb);
            }
#pragma unroll
            for (int mt = 0; mt < 2; ++mt)
#pragma unroll
                for (int nt = 0; nt < 4; ++nt) {
                    const uint32_t* bh = &bhi[nt >> 1][(nt & 1) * 2];
                    const uint32_t* bl = &blo[nt >> 1][(nt & 1) * 2];
                    mma16816(c[mt][nt], ahi[mt], bh);
                    mma16816(c[mt][nt], ahi[mt], bl);
                    mma16816(c[mt][nt], alo[mt], bh);
                }
        }

        float* C = h2 ? Ps : Pd;
#pragma unroll
        for (int mt = 0; mt < 2; ++mt) {
            int mrow = m0 + warp_m * 32 + mt * 16 + gr;
#pragma unroll
            for (int nt = 0; nt < 4; ++nt) {
                int n = warp_n * 32 + nt * 8 + gc;
                *(float2*)(C + (size_t)mrow * 128 + n) =
                    make_float2(c[mt][nt][0], c[mt][nt][1]);
                *(float2*)(C + (size_t)(mrow + 8) * 128 + n) =
                    make_float2(c[mt][nt][2], c[mt][nt][3]);
            }
        }
    }
}

// ---------------- edge GEMM: persistent, ALL-warp cooperative (no specialization) ----
__global__ __launch_bounds__(512, 1)
void tc_edge(const float* __restrict__ Pd, const float* __restrict__ Ps,
             const char* __restrict__ Wt,
             const float* __restrict__ preBias, const float* __restrict__ postBias,
             float* __restrict__ C,
             const int* __restrict__ dstIdx, const int* __restrict__ srcIdx,
             float* __restrict__ zeroAcc) {
    extern __shared__ char dyn[];
    const int tid = threadIdx.x;
    const int wid = tid >> 5;
    const int lid = tid & 31;
    uint32_t dyn_u32 = smem_u32(dyn);
    uint32_t pad = ((dyn_u32 + 1023u) & ~1023u) - dyn_u32;
    char* tiles = dyn + pad;
    uint32_t tiles_u32 = dyn_u32 + pad;
    // A hi @0, lo @32K, W hi @64K, lo @96K

    if (zeroAcc && blockIdx.x == 0) {
        ((float4*)zeroAcc)[tid] = make_float4(0.f, 0.f, 0.f, 0.f);
        ((float4*)zeroAcc)[tid + 512] = make_float4(0.f, 0.f, 0.f, 0.f);
    }
    {
        const float4* wsrc = (const float4*)Wt;
        float4* wdst = (float4*)(tiles + 65536);
#pragma unroll
        for (int j = 0; j < 8; ++j)
            wdst[tid + j * 512] = wsrc[tid + j * 512];
    }

    // mma roles (pdps-style 4x4 warp grid, 32x32 per warp)
    const int warp_m = wid & 3;
    const int warp_n = wid >> 2;
    const int quad = lid >> 3;
    const int lrow = lid & 7;
    const int a_rl = (quad & 1) * 8 + lrow;
    const int akq  = quad >> 1;
    const int b_rl = (quad >> 1) * 8 + lrow;
    const int bkq  = quad & 1;
    uint32_t arow256[2]; int ar7[2];
#pragma unroll
    for (int mt = 0; mt < 2; ++mt) {
        int rr = warp_m * 32 + mt * 16 + a_rl;
        arow256[mt] = (uint32_t)rr * 256; ar7[mt] = rr & 7;
    }
    uint32_t brow256[2]; int br7[2];
#pragma unroll
    for (int pj = 0; pj < 2; ++pj) {
        int rr = warp_n * 32 + pj * 16 + b_rl;
        brow256[pj] = (uint32_t)rr * 256; br7[pj] = rr & 7;
    }
    const int gr = lid >> 2;
    const int gc = (lid & 3) << 1;
    float2 pbr[4];
#pragma unroll
    for (int nt = 0; nt < 4; ++nt)
        pbr[nt] = *(const float2*)(postBias + warp_n * 32 + nt * 8 + gc);

    // stage roles
    const int sr  = tid >> 3;
    const int ch8 = tid & 7;
    float4 bias4[4];
#pragma unroll
    for (int j = 0; j < 4; ++j)
        bias4[j] = *(const float4*)(preBias + (ch8 + j * 8) * 4);

    const int NT = N_EDGES / 128;
    __syncthreads();   // W ready

    for (int tile = blockIdx.x; tile < NT; tile += gridDim.x) {
        // ---- stage: gather + relu + split into A tile ----
#pragma unroll
        for (int pass = 0; pass < 2; ++pass) {
            const int r = sr + pass * 64;
            const int e = tile * 128 + r;
            const float* pd = Pd + (size_t)dstIdx[e] * 128;
            const float* ps = Ps + (size_t)srcIdx[e] * 128;
            const int r7 = r & 7;
            const uint32_t r256 = (uint32_t)r * 256;
#pragma unroll
            for (int j = 0; j < 4; ++j) {
                const int c4 = (ch8 + j * 8) * 4;
                float4 a = *(const float4*)(pd + c4);
                float4 s = *(const float4*)(ps + c4);
                float4 v;
                v.x = fmaxf(a.x + s.x + bias4[j].x, 0.f);
                v.y = fmaxf(a.y + s.y + bias4[j].y, 0.f);
                v.z = fmaxf(a.z + s.z + bias4[j].z, 0.f);
                v.w = fmaxf(a.w + s.w + bias4[j].w, 0.f);
                uint2 hv, lv;
                split4(v, hv, lv);
                uint32_t off = r256 + ((((c4 >> 3) ^ r7) << 4) | ((c4 & 7) << 1));
                *(uint2*)(tiles + off) = hv;
                *(uint2*)(tiles + 32768 + off) = lv;
            }
        }
        __syncthreads();

        // ---- mma: pdps mainloop clone ----
        float c[2][4][4];
#pragma unroll
        for (int mt = 0; mt < 2; ++mt)
#pragma unroll
            for (int nt = 0; nt < 4; ++nt)
#pragma unroll
                for (int i = 0; i < 4; ++i) c[mt][nt][i] = 0.f;

#pragma unroll
        for (int ks = 0; ks < 8; ++ks) {
            const int kb = ks * 2;
            uint32_t ahi[2][4], alo[2][4], bhi[2][4], blo[2][4];
#pragma unroll
            for (int mt = 0; mt < 2; ++mt) {
                uint32_t sw = (uint32_t)(((kb + akq) ^ ar7[mt]) << 4);
                ldmx4(ahi[mt], tiles_u32 + arow256[mt] + sw);
                ldmx4(alo[mt], tiles_u32 + 32768 + arow256[mt] + sw);
            }
#pragma unroll
            for (int pj = 0; pj < 2; ++pj) {
                uint32_t swb = (uint32_t)(((kb + bkq) ^ br7[pj]) << 4);
                ldmx4(bhi[pj], tiles_u32 + 65536 + brow256[pj] + swb);
                ldmx4(blo[pj], tiles_u32 + 98304 + brow256[pj] + swb);
            }
#pragma unroll
            for (int mt = 0; mt < 2; ++mt)
#pragma unroll
                for (int nt = 0; nt < 4; ++nt) {
                    const uint32_t* bh = &bhi[nt >> 1][(nt & 1) * 2];
                    const uint32_t* bl = &blo[nt >> 1][(nt & 1) * 2];
                    mma16816(c[mt][nt], ahi[mt], bh);
                    mma16816(c[mt][nt], ahi[mt], bl);
                    mma16816(c[mt][nt], alo[mt], bh);
                }
        }

        // ---- epilogue: scatter-add (rows warp_m*32.., cols warp_n*32..) ----
#pragma unroll
        for (int mt = 0; mt < 2; ++mt) {
            const int lr0 = warp_m * 32 + mt * 16 + gr;
            const int d0 = dstIdx[tile * 128 + lr0];
            const int d1 = dstIdx[tile * 128 + lr0 + 8];
#pragma unroll
            for (int nt = 0; nt < 4; ++nt) {
                const int n = warp_n * 32 + nt * 8 + gc;
                float o0 = fmaxf(c[mt][nt][0] + pbr[nt].x, 0.f);
                float o1 = fmaxf(c[mt][nt][1] + pbr[nt].y, 0.f);
                float o2 = fmaxf(c[mt][nt][2] + pbr[nt].x, 0.f);
                float o3 = fmaxf(c[mt][nt][3] + pbr[nt].y, 0.f);
                if (o0 != 0.f || o1 != 0.f) red_add_v2(C + (size_t)d0 * 128 + n, o0, o1);
                if (o2 != 0.f || o3 != 0.f) red_add_v2(C + (size_t)d1 * 128 + n, o2, o3);
            }
        }
        __syncthreads();   // A tile free for next stage
    }
}

// ---------------- fused U1+U2 ----------------
template<int NORM>
__global__ __launch_bounds__(512, 1)
void tc_u1u2(const float* __restrict__ A0, const float* __restrict__ A1,
             const char* __restrict__ Wt1, const float* __restrict__ BU1,
             const char* __restrict__ Wt2, const float* __restrict__ BU2,
             float* __restrict__ C2, const float* __restrict__ accPrev,
             float* __restrict__ accCur, float* __restrict__ aggNext) {
    extern __shared__ char dyn[];
    __shared__ float s_stats[256];
    const int tid = threadIdx.x;
    const int wid = tid >> 5;
    const int lid = tid & 31;
    const int m0  = blockIdx.x * 128;
    uint32_t dyn_u32 = smem_u32(dyn);
    uint32_t pad = ((dyn_u32 + 1023u) & ~1023u) - dyn_u32;
    char* tiles = dyn + pad;
    uint32_t tiles_u32 = dyn_u32 + pad;

    const int warp_m = wid & 3;
    const int warp_n = wid >> 2;
    const int quad = lid >> 3;
    const int lrow = lid & 7;
    const int a_rl = (quad & 1) * 8 + lrow;
    const int akq  = quad >> 1;
    const int b_rl = (quad >> 1) * 8 + lrow;
    const int bkq  = quad & 1;
    uint32_t arow256[2]; int ar7[2];
#pragma unroll
    for (int mt = 0; mt < 2; ++mt) {
        int rr = warp_m * 32 + mt * 16 + a_rl;
        arow256[mt] = (uint32_t)rr * 256; ar7[mt] = rr & 7;
    }
    uint32_t brow256[2]; int br7[2];
#pragma unroll
    for (int pj = 0; pj < 2; ++pj) {
        int rr = warp_n * 32 + pj * 16 + b_rl;
        brow256[pj] = (uint32_t)rr * 256; br7[pj] = rr & 7;
    }
    const int gr = lid >> 2;
    const int gc = (lid & 3) << 1;

    if (NORM) {
        compute_stats(accPrev, m0 >> 10, s_stats, tid);
        __syncthreads();
    }

    // ======== U1 ========
    float c[2][4][4];
#pragma unroll
    for (int mt = 0; mt < 2; ++mt)
#pragma unroll
        for (int nt = 0; nt < 4; ++nt)
#pragma unroll
            for (int i = 0; i < 4; ++i) c[mt][nt][i] = 0.f;

    for (int p = 0; p < 2; ++p) {
        if (p) __syncthreads();
        if (p == 0)
            stage_rows<512, 128, NORM>(A0, m0, tiles, tiles + 32768, s_stats, tid);
        else {
            stage_rows<512, 128, 0>(A1, m0, tiles, tiles + 32768, nullptr, tid);
            const int sr = tid >> 3, ch8 = tid & 7;
#pragma unroll
            for (int pass = 0; pass < 2; ++pass) {
                int node = m0 + sr + pass * 64;
                float4* zr = (float4*)(aggNext + (size_t)node * 128) + ch8;
#pragma unroll
                for (int j = 0; j < 4; ++j)
                    zr[j * 8] = make_float4(0.f, 0.f, 0.f, 0.f);
            }
        }
        {
            const float4* wsrc = (const float4*)(Wt1 + (size_t)p * 65536);
            float4* wdst = (float4*)(tiles + 65536);
#pragma unroll
            for (int j = 0; j < 8; ++j)
                wdst[tid + j * 512] = wsrc[tid + j * 512];
        }
        __syncthreads();

#pragma unroll
        for (int ks = 0; ks < 8; ++ks) {
            const int kb = ks * 2;
            uint32_t ahi[2][4], alo[2][4], bhi[2][4], blo[2][4];
#pragma unroll
            for (int mt = 0; mt < 2; ++mt) {
                uint32_t sw = (uint32_t)(((kb + akq) ^ ar7[mt]) << 4);
                ldmx4(ahi[mt], tiles_u32 + arow256[mt] + sw);
                ldmx4(alo[mt], tiles_u32 + 32768 + arow256[mt] + sw);
            }
#pragma unroll
            for (int pj = 0; pj < 2; ++pj) {
                uint32_t swb = (uint32_t)(((kb + bkq) ^ br7[pj]) << 4);
                ldmx4(bhi[pj], tiles_u32 + 65536 + brow256[pj] + swb);
                ldmx4(blo[pj], tiles_u32 + 98304 + brow256[pj] + swb);
            }
#pragma unroll
            for (int mt = 0; mt < 2; ++mt)
#pragma unroll
                for (int nt = 0; nt < 4; ++nt) {
                    const uint32_t* bh = &bhi[nt >> 1][(nt & 1) * 2];
                    const uint32_t* bl = &blo[nt >> 1][(nt & 1) * 2];
                    mma16816(c[mt][nt], ahi[mt], bh);
                    mma16816(c[mt][nt], ahi[mt], bl);
                    mma16816(c[mt][nt], alo[mt], bh);
                }
        }
    }

    // ======== U1 epilogue -> smem bf16 t1 tile ========
    __syncthreads();
#pragma unroll
    for (int mt = 0; mt < 2; ++mt) {
        const int r1 = warp_m * 32 + mt * 16 + gr;
        const int r2 = r1 + 8;
#pragma unroll
        for (int nt = 0; nt < 4; ++nt) {
            const int n = warp_n * 32 + nt * 8 + gc;
            float2 pb = *(const float2*)(BU1 + n);
            float o0 = fmaxf(c[mt][nt][0] + pb.x, 0.f);
            float o1 = fmaxf(c[mt][nt][1] + pb.y, 0.f);
            float o2 = fmaxf(c[mt][nt][2] + pb.x, 0.f);
            float o3 = fmaxf(c[mt][nt][3] + pb.y, 0.f);
            uint32_t hv, lv;
            split2(o0, o1, hv, lv);
            uint32_t off1 = (uint32_t)(r1 * 256 + ((((n >> 3) ^ (r1 & 7)) << 4) | ((n & 7) << 1)));
            *(uint32_t*)(tiles + off1) = hv;
            *(uint32_t*)(tiles + 32768 + off1) = lv;
            split2(o2, o3, hv, lv);
            uint32_t off2 = (uint32_t)(r2 * 256 + ((((n >> 3) ^ (r2 & 7)) << 4) | ((n & 7) << 1)));
            *(uint32_t*)(tiles + off2) = hv;
            *(uint32_t*)(tiles + 32768 + off2) = lv;
        }
    }
    {
        const float4* wsrc = (const float4*)Wt2;
        float4* wdst = (float4*)(tiles + 65536);
#pragma unroll
        for (int j = 0; j < 8; ++j)
            wdst[tid + j * 512] = wsrc[tid + j * 512];
    }
    __syncthreads();

    // ======== U2 ========
    float c2[2][4][4];
#pragma unroll
    for (int mt = 0; mt < 2; ++mt)
#pragma unroll
        for (int nt = 0; nt < 4; ++nt)
#pragma unroll
            for (int i = 0; i < 4; ++i) c2[mt][nt][i] = 0.f;

#pragma unroll
    for (int ks = 0; ks < 8; ++ks) {
        const int kb = ks * 2;
        uint32_t ahi[2][4], alo[2][4], bhi[2][4], blo[2][4];
#pragma unroll
        for (int mt = 0; mt < 2; ++mt) {
            uint32_t sw = (uint32_t)(((kb + akq) ^ ar7[mt]) << 4);
            ldmx4(ahi[mt], tiles_u32 + arow256[mt] + sw);
            ldmx4(alo[mt], tiles_u32 + 32768 + arow256[mt] + sw);
        }
#pragma unroll
        for (int pj = 0; pj < 2; ++pj) {
            uint32_t swb = (uint32_t)(((kb + bkq) ^ br7[pj]) << 4);
            ldmx4(bhi[pj], tiles_u32 + 65536 + brow256[pj] + swb);
            ldmx4(blo[pj], tiles_u32 + 98304 + brow256[pj] + swb);
        }
#pragma unroll
        for (int mt = 0; mt < 2; ++mt)
#pragma unroll
            for (int nt = 0; nt < 4; ++nt) {
                const uint32_t* bh = &bhi[nt >> 1][(nt & 1) * 2];
                const uint32_t* bl = &blo[nt >> 1][(nt & 1) * 2];
                mma16816(c2[mt][nt], ahi[mt], bh);
                mma16816(c2[mt][nt], ahi[mt], bl);
                mma16816(c2[mt][nt], alo[mt], bh);
            }
    }

    // ======== U2 epilogue ========
    const int batch = m0 >> 10;
    float* accS = accCur + batch * 128;
    float* accQ = accCur + NBATCH * NHID + batch * 128;
#pragma unroll
    for (int nt = 0; nt < 4; ++nt) {
        const int n = warp_n * 32 + nt * 8 + gc;
        float2 pb = *(const float2*)(BU2 + n);
        float s0 = 0.f, s1 = 0.f, q0 = 0.f, q1 = 0.f;
#pragma unroll
        for (int mt = 0; mt < 2; ++mt) {
            int mrow = m0 + warp_m * 32 + mt * 16 + gr;
            float o0 = fmaxf(c2[mt][nt][0] + pb.x, 0.f);
            float o1 = fmaxf(c2[mt][nt][1] + pb.y, 0.f);
            float o2 = fmaxf(c2[mt][nt][2] + pb.x, 0.f);
            float o3 = fmaxf(c2[mt][nt][3] + pb.y, 0.f);
            *(float2*)(C2 + (size_t)mrow * 128 + n)       = make_float2(o0, o1);
            *(float2*)(C2 + (size_t)(mrow + 8) * 128 + n) = make_float2(o2, o3);
            s0 += o0 + o2;
            s1 += o1 + o3;
            q0 += o0 * o0 + o2 * o2;
            q1 += o1 * o1 + o3 * o3;
        }
#pragma unroll
        for (int off = 4; off < 32; off <<= 1) {
            s0 += __shfl_xor_sync(0xFFFFFFFFu, s0, off);
            s1 += __shfl_xor_sync(0xFFFFFFFFu, s1, off);
            q0 += __shfl_xor_sync(0xFFFFFFFFu, q0, off);
            q1 += __shfl_xor_sync(0xFFFFFFFFu, q1, off);
        }
        if (lid < 4) {
            red_add_v2(accS + n, s0, s1);
            red_add_v2(accQ + n, q0, q1);
        }
    }
}

// ---------------- decoder / discrepancy / final ----------------
__global__ void decoder_kernel(const float* __restrict__ H,
                               const float* __restrict__ acc,
                               const float* __restrict__ W,
                               const float* __restrict__ B,
                               float* __restrict__ GX,
                               float* __restrict__ x_out) {
    int gthread = blockIdx.x * blockDim.x + threadIdx.x;
    int n = gthread >> 5;
    int lane = threadIdx.x & 31;
    if (n >= N_NODES) return;
    const float* hr = H + (size_t)n * 128;
    const float* accS = acc + (n >> 10) * 128;
    const float* accQ = accS + NBATCH * NHID;
    float a0 = 0.f, a1 = 0.f, a2 = 0.f, a3 = 0.f;
#pragma unroll
    for (int k = 0; k < 128; k += 32) {
        float s = accS[k + lane];
        float q = accQ[k + lane];
        float mean = s * (1.0f / NSAMPLES);
        float var = q * (1.0f / NSAMPLES) - mean * mean;
        float hv = (hr[k + lane] - mean) * rsqrtf(var + EPSV);
        float4 w = ((const float4*)W)[k + lane];
        a0 += hv * w.x;
        a1 += hv * w.y;
        a2 += hv * w.z;
        a3 += hv * w.w;
    }
#pragma unroll
    for (int off = 16; off > 0; off >>= 1) {
        a0 += __shfl_xor_sync(0xFFFFFFFFu, a0, off);
        a1 += __shfl_xor_sync(0xFFFFFFFFu, a1, off);
        a2 += __shfl_xor_sync(0xFFFFFFFFu, a2, off);
        a3 += __shfl_xor_sync(0xFFFFFFFFu, a3, off);
    }
    if (lane == 0) {
        float z0 = 1.f / (1.f + expf(-(a0 + B[0])));
        float z1 = 1.f / (1.f + expf(-(a1 + B[1])));
        float z2 = 1.f / (1.f + expf(-(a2 + B[2])));
        float z3 = 1.f / (1.f + expf(-(a3 + B[3])));
        ((float4*)GX)[n] = make_float4(z0, z1, z2, z3);
        if (x_out) {
            x_out[n * 4 + 0] = z0;
            x_out[n * 4 + 1] = z1;
            x_out[n * 4 + 2] = z2;
            x_out[n * 4 + 3] = z3;
        }
    }
}

__global__ void disc_kernel(const float* __restrict__ GX) {
    __shared__ float4 sx[NSAMPLES];
    __shared__ float red1[128];
    __shared__ float red2[128];
    int b = blockIdx.x;
    int chunk = blockIdx.y;
    int tid = threadIdx.x;
    const float4* xb = (const float4*)GX + (size_t)b * NSAMPLES;
    for (int i = tid; i < NSAMPLES; i += 128) sx[i] = xb[i];
    __syncthreads();
    int i = chunk * 128 + tid;
    float4 xi = sx[i];
    float p1 = (1.f - xi.x * xi.x) * (1.f - xi.y * xi.y) *
               (1.f - xi.z * xi.z) * (1.f - xi.w * xi.w);
    float s2a = 0.f, s2b = 0.f, s2c = 0.f, s2d = 0.f;
#pragma unroll 2
    for (int j = 0; j < NSAMPLES; j += 4) {
        float4 x0 = sx[j];
        float4 x1 = sx[j + 1];
        float4 x2 = sx[j + 2];
        float4 x3 = sx[j + 3];
        s2a += (1.f - fmaxf(xi.x, x0.x)) * (1.f - fmaxf(xi.y, x0.y)) *
               (1.f - fmaxf(xi.z, x0.z)) * (1.f - fmaxf(xi.w, x0.w));
        s2b += (1.f - fmaxf(xi.x, x1.x)) * (1.f - fmaxf(xi.y, x1.y)) *
               (1.f - fmaxf(xi.z, x1.z)) * (1.f - fmaxf(xi.w, x1.w));
        s2c += (1.f - fmaxf(xi.x, x2.x)) * (1.f - fmaxf(xi.y, x2.y)) *
               (1.f - fmaxf(xi.z, x2.z)) * (1.f - fmaxf(xi.w, x2.w));
        s2d += (1.f - fmaxf(xi.x, x3.x)) * (1.f - fmaxf(xi.y, x3.y)) *
               (1.f - fmaxf(xi.z, x3.z)) * (1.f - fmaxf(xi.w, x3.w));
    }
    float s2 = (s2a + s2b) + (s2c + s2d);
    red1[tid] = p1;
    red2[tid] = s2;
    __syncthreads();
    for (int s = 64; s > 0; s >>= 1) {
        if (tid < s) {
            red1[tid] += red1[tid + s];
            red2[tid] += red2[tid + s];
        }
        __syncthreads();
    }
    if (tid == 0) {
        atomicAdd(&g_dsum[b], red1[0]);
        atomicAdd(&g_dsum[16 + b], red2[0]);
    }
}

__global__ void final_kernel(float* __restrict__ loss_out) {
    if (threadIdx.x == 0 && blockIdx.x == 0) {
        float acc = 0.f;
        const float invN = 1.0f / (float)NSAMPLES;
        for (int b = 0; b < NBATCH; ++b) {
            float s1 = g_dsum[b];
            float s2 = g_dsum[16 + b];
            float v = (1.0f / 81.0f) - invN * 0.125f * s1 + s2 * invN * invN;
            acc += sqrtf(v);
        }
        float loss = acc / (float)NBATCH;
        if (loss_out) *loss_out = loss;
    }
}

// ---------------- launch ----------------
extern "C" void kernel_launch(void* const* d_in, const int* in_sizes, int n_in,
                              void* d_out, int out_size) {
    const float *X, *enc_w, *enc_b, *dec_w, *dec_b;
    const float *m1w, *m1b, *m2w, *m2b, *u1w, *u1b, *u2w, *u2b;
    const int* ei = (const int*)d_in[1];
    X = (const float*)d_in[0];
    bool dictOrder = (in_sizes[5] == 512);
    if (dictOrder) {
        enc_w = (const float*)d_in[3];  enc_b = (const float*)d_in[4];
        dec_w = (const float*)d_in[5];  dec_b = (const float*)d_in[6];
        m1w = (const float*)d_in[7];    m1b = (const float*)d_in[8];
        m2w = (const float*)d_in[9];    m2b = (const float*)d_in[10];
        u1w = (const float*)d_in[11];   u1b = (const float*)d_in[12];
        u2w = (const float*)d_in[13];   u2b = (const float*)d_in[14];
    } else {
        enc_w = (const float*)d_in[3];  enc_b = (const float*)d_in[4];
        m1w = (const float*)d_in[5];    m1b = (const float*)d_in[6];
        m2w = (const float*)d_in[7];    m2b = (const float*)d_in[8];
        u1w = (const float*)d_in[9];    u1b = (const float*)d_in[10];
        u2w = (const float*)d_in[11];   u2b = (const float*)d_in[12];
        dec_w = (const float*)d_in[13]; dec_b = (const float*)d_in[14];
    }
    const int* src = ei;
    const int* dst = ei + N_EDGES;

    void* p;
    float *h_, *Pd, *Ps, *aggA, *aggB, *t2, *gx, *naccA, *naccB;
    char* wt;
    cudaGetSymbolAddress(&p, g_h);      h_   = (float*)p;
    cudaGetSymbolAddress(&p, g_Pd);     Pd   = (float*)p;
    cudaGetSymbolAddress(&p, g_Ps);     Ps   = (float*)p;
    cudaGetSymbolAddress(&p, g_agg);    aggA = (float*)p;
    cudaGetSymbolAddress(&p, g_agg2);   aggB = (float*)p;
    cudaGetSymbolAddress(&p, g_t2);     t2   = (float*)p;
    cudaGetSymbolAddress(&p, g_x);      gx   = (float*)p;
    cudaGetSymbolAddress(&p, g_naccA);  naccA = (float*)p;
    cudaGetSymbolAddress(&p, g_naccB);  naccB = (float*)p;
    cudaGetSymbolAddress(&p, g_wt);     wt   = (char*)p;
    float* aggs[2]  = {aggA, aggB};
    float* naccs[2] = {naccA, naccB};

    float* out = (float*)d_out;
    float* loss_out;
    float* x_out;
    if (out_size >= N_NODES * DIMX + 1) { loss_out = out; x_out = out + 1; }
    else if (out_size == N_NODES * DIMX) { loss_out = nullptr; x_out = out; }
    else { loss_out = out; x_out = nullptr; }

    cudaFuncSetAttribute(tc_pdps<0>, cudaFuncAttributeMaxDynamicSharedMemorySize, PDPS_SMEM);
    cudaFuncSetAttribute(tc_pdps<1>, cudaFuncAttributeMaxDynamicSharedMemorySize, PDPS_SMEM);
    cudaFuncSetAttribute(tc_edge,    cudaFuncAttributeMaxDynamicSharedMemorySize, EDGE_SMEM);
    cudaFuncSetAttribute(tc_u1u2<0>, cudaFuncAttributeMaxDynamicSharedMemorySize, U1_SMEM);
    cudaFuncSetAttribute(tc_u1u2<1>, cudaFuncAttributeMaxDynamicSharedMemorySize, U1_SMEM);

    // ---- weight prep ----
    PrepJobs jobs;
    for (int l = 0; l < NLAYERS; ++l) {
        char* lb = wt + (size_t)l * WT_LAYER_STRIDE;
        jobs.src[l*5+0] = m1w + (size_t)l * 256 * 128;            jobs.dst[l*5+0] = lb + WT_W1A; jobs.nelem[l*5+0] = 128*128;
        jobs.src[l*5+1] = m1w + (size_t)l * 256 * 128 + 128*128;  jobs.dst[l*5+1] = lb + WT_W1B; jobs.nelem[l*5+1] = 128*128;
        jobs.src[l*5+2] = m2w + (size_t)l * 128 * 128;            jobs.dst[l*5+2] = lb + WT_W2;  jobs.nelem[l*5+2] = 128*128;
        jobs.src[l*5+3] = u1w + (size_t)l * 256 * 128;            jobs.dst[l*5+3] = lb + WT_U1;  jobs.nelem[l*5+3] = 256*128;
        jobs.src[l*5+4] = u2w + (size_t)l * 128 * 128;            jobs.dst[l*5+4] = lb + WT_U2;  jobs.nelem[l*5+4] = 128*128;
    }
    prep_w_all<<<dim3(128, 15), 256>>>(jobs);

    encoder_kernel<<<(N_NODES * NHID) / 256, 256>>>(X, enc_w, enc_b, h_);

    for (int l = 0; l < NLAYERS; ++l) {
        char* lb = wt + (size_t)l * WT_LAYER_STRIDE;
        const float* B1  = m1b + l * 128;
        const float* B2  = m2b + l * 128;
        const float* BU1 = u1b + l * 128;
        const float* BU2 = u2b + l * 128;
        const float* Aprev = (l == 0) ? h_ : t2;
        float* aggCur  = aggs[l & 1];
        float* aggNext = aggs[(l + 1) & 1];
        float* accPrev = (l == 0) ? nullptr : naccs[(l - 1) & 1];
        float* accCur  = naccs[l & 1];
        float* zeroAcc = (l == 2) ? accCur : nullptr;

        if (l == 0)
            tc_pdps<0><<<128, 512, PDPS_SMEM>>>(Aprev, lb + WT_W1A, Pd, Ps, nullptr);
        else
            tc_pdps<1><<<128, 512, PDPS_SMEM>>>(Aprev, lb + WT_W1A, Pd, Ps, accPrev);

        tc_edge<<<148, 512, EDGE_SMEM>>>(Pd, Ps, lb + WT_W2, B1, B2, aggCur, dst, src, zeroAcc);

        if (l == 0)
            tc_u1u2<0><<<128, 512, U1_SMEM>>>(Aprev, aggCur, lb + WT_U1, BU1,
                                              lb + WT_U2, BU2, t2, nullptr, accCur, aggNext);
        else
            tc_u1u2<1><<<128, 512, U1_SMEM>>>(Aprev, aggCur, lb + WT_U1, BU1,
                                              lb + WT_U2, BU2, t2, accPrev, accCur, aggNext);
    }

    decoder_kernel<<<(N_NODES * 32) / 256, 256>>>(t2, naccs[(NLAYERS - 1) & 1],
                                                  dec_w, dec_b, gx, x_out);
    disc_kernel<<<dim3(NBATCH, 8), 128>>>(gx);
    final_kernel<<<1, 1>>>(loss_out);
}

// round 14
// speedup vs baseline: 1.0632x; 1.0632x over previous
#include <cuda_runtime.h>
#include <cuda_bf16.h>
#include <math.h>
#include <stdint.h>

// ---------------- problem constants ----------------
#define N_NODES   16384
#define N_EDGES   262144
#define NHID      128
#define NLAYERS   3
#define NBATCH    16
#define NSAMPLES  1024
#define DIMX      4
#define EPSV      1e-5f

#define WT_LAYER_STRIDE 393216
#define WT_W1A 0
#define WT_W1B 65536
#define WT_W2  131072
#define WT_U1  196608
#define WT_U2  327680

#define PDPS_SMEM  197632   // 1K pad + A 64K + W1a/W1b hi/lo 128K
#define EDGE_SMEM  197632   // 1K pad + 2 A bufs (2*64K) + W 64K
#define U1_SMEM    132096   // 1K pad + A 64K + W 64K

// ---------------- device scratch ----------------
__device__ float g_h [N_NODES * NHID];
__device__ float g_Pd[N_NODES * NHID];
__device__ float g_Ps[N_NODES * NHID];
__device__ float g_agg [N_NODES * NHID];
__device__ float g_agg2[N_NODES * NHID];
__device__ float g_t2[N_NODES * NHID];
__device__ float g_x [N_NODES * DIMX];
__device__ float g_naccA[2 * NBATCH * NHID];
__device__ float g_naccB[2 * NBATCH * NHID];
__device__ float g_dsum[32];
__device__ char  g_wt[NLAYERS * WT_LAYER_STRIDE];

// ---------------- helpers ----------------
__device__ __forceinline__ uint32_t smem_u32(const void* p) {
    uint32_t a;
    asm("{ .reg .u64 t; cvta.to.shared.u64 t, %1; cvt.u32.u64 %0, t; }" : "=r"(a) : "l"(p));
    return a;
}
__device__ __forceinline__ void red_add_v2(float* p, float a, float b) {
    asm volatile("red.global.add.v2.f32 [%0], {%1,%2};"
                 :: "l"(p), "f"(a), "f"(b) : "memory");
}
__device__ __forceinline__ uint32_t pack2(__nv_bfloat16 a, __nv_bfloat16 b) {
    return (uint32_t)__bfloat16_as_ushort(a) | ((uint32_t)__bfloat16_as_ushort(b) << 16);
}
__device__ __forceinline__ void ldmx4(uint32_t* r, uint32_t addr) {
    asm volatile("ldmatrix.sync.aligned.m8n8.x4.shared.b16 {%0,%1,%2,%3}, [%4];"
                 : "=r"(r[0]), "=r"(r[1]), "=r"(r[2]), "=r"(r[3]) : "r"(addr));
}
__device__ __forceinline__ void mma16816(float* c, const uint32_t* a, const uint32_t* b) {
    asm volatile("mma.sync.aligned.m16n8k16.row.col.f32.bf16.bf16.f32 "
                 "{%0,%1,%2,%3}, {%4,%5,%6,%7}, {%8,%9}, {%0,%1,%2,%3};"
                 : "+f"(c[0]), "+f"(c[1]), "+f"(c[2]), "+f"(c[3])
                 : "r"(a[0]), "r"(a[1]), "r"(a[2]), "r"(a[3]), "r"(b[0]), "r"(b[1]));
}
#define BAR_SYNC(id)   asm volatile("bar.sync %0, 512;"   :: "r"(id) : "memory")
#define BAR_ARRIVE(id) asm volatile("bar.arrive %0, 512;" :: "r"(id) : "memory")

__device__ __forceinline__ void split4(float4 v, uint2& hv, uint2& lv) {
    __nv_bfloat16 h0 = __float2bfloat16(v.x);
    __nv_bfloat16 h1 = __float2bfloat16(v.y);
    __nv_bfloat16 h2 = __float2bfloat16(v.z);
    __nv_bfloat16 h3 = __float2bfloat16(v.w);
    __nv_bfloat16 l0 = __float2bfloat16(v.x - __bfloat162float(h0));
    __nv_bfloat16 l1 = __float2bfloat16(v.y - __bfloat162float(h1));
    __nv_bfloat16 l2 = __float2bfloat16(v.z - __bfloat162float(h2));
    __nv_bfloat16 l3 = __float2bfloat16(v.w - __bfloat162float(h3));
    hv = make_uint2(pack2(h0, h1), pack2(h2, h3));
    lv = make_uint2(pack2(l0, l1), pack2(l2, l3));
}
__device__ __forceinline__ void split2(float a, float b, uint32_t& hv, uint32_t& lv) {
    __nv_bfloat16 h0 = __float2bfloat16(a);
    __nv_bfloat16 h1 = __float2bfloat16(b);
    __nv_bfloat16 l0 = __float2bfloat16(a - __bfloat162float(h0));
    __nv_bfloat16 l1 = __float2bfloat16(b - __bfloat162float(h1));
    hv = pack2(h0, h1);
    lv = pack2(l0, l1);
}

__device__ __forceinline__ void compute_stats(const float* __restrict__ acc,
                                              int batch, float* s_stats, int tid) {
    if (tid < 128) {
        float s = acc[batch * 128 + tid];
        float q = acc[NBATCH * NHID + batch * 128 + tid];
        float mean = s * (1.0f / NSAMPLES);
        float var = q * (1.0f / NSAMPLES) - mean * mean;
        s_stats[tid] = mean;
        s_stats[128 + tid] = rsqrtf(var + EPSV);
    }
}

// ---------------- weight prep ----------------
struct PrepJobs {
    const float* src[15];
    char* dst[15];
    int nelem[15];
};
__global__ void prep_w_all(PrepJobs jobs) {
    int m = blockIdx.y;
    int idx = blockIdx.x * 256 + threadIdx.x;
    if (idx >= jobs.nelem[m]) return;
    const float* W = jobs.src[m];
    char* out = jobs.dst[m];
    int k = idx >> 7, n = idx & 127;
    float w = W[idx];
    __nv_bfloat16 hi = __float2bfloat16(w);
    __nv_bfloat16 lo = __float2bfloat16(w - __bfloat162float(hi));
    int phase = k >> 7, kk = k & 127;
    uint32_t off = (uint32_t)(n * 256 + ((((kk >> 3) ^ (n & 7)) << 4) | ((kk & 7) << 1)));
    *(__nv_bfloat16*)(out + (size_t)phase * 65536 + off) = hi;
    *(__nv_bfloat16*)(out + (size_t)phase * 65536 + 32768 + off) = lo;
}

// ---------------- encoder ----------------
__global__ void encoder_kernel(const float* __restrict__ X,
                               const float* __restrict__ W,
                               const float* __restrict__ B,
                               float* __restrict__ H) {
    int idx = blockIdx.x * blockDim.x + threadIdx.x;
    int n = idx >> 7;
    int c = idx & 127;
    float4 xv = ((const float4*)X)[n];
    float v = B[c];
    v += xv.x * W[c];
    v += xv.y * W[128 + c];
    v += xv.z * W[256 + c];
    v += xv.w * W[384 + c];
    H[idx] = v;
    g_agg[idx] = 0.f;
    if (idx < 2 * NBATCH * NHID) { g_naccA[idx] = 0.f; g_naccB[idx] = 0.f; }
    if (idx < 32) g_dsum[idx] = 0.f;
}

// ---------------- coalesced staging ----------------
template<int NTHREADS, int NROWS, int NORM>
__device__ __forceinline__ void stage_rows(
    const float* __restrict__ Abase, int row0,
    char* __restrict__ Ahi, char* __restrict__ Alo,
    const float* __restrict__ stats, int tid)
{
    const int sr  = tid >> 3;
    const int ch8 = tid & 7;
    const int ROWS_PER_PASS = NTHREADS / 8;
    const int NPASS = NROWS / ROWS_PER_PASS;
#pragma unroll
    for (int pass = 0; pass < NPASS; ++pass) {
        const int r = sr + pass * ROWS_PER_PASS;
        const int node = row0 + r;
        const float* arow = Abase + (size_t)node * 128;
        const int r7 = r & 7;
        const uint32_t r256 = (uint32_t)r * 256;
#pragma unroll
        for (int j = 0; j < 4; ++j) {
            const int c4 = (ch8 + j * 8) * 4;
            float4 v = *(const float4*)(arow + c4);
            if (NORM) {
                float4 m  = *(const float4*)(stats + c4);
                float4 iv = *(const float4*)(stats + 128 + c4);
                v.x = (v.x - m.x) * iv.x;
                v.y = (v.y - m.y) * iv.y;
                v.z = (v.z - m.z) * iv.z;
                v.w = (v.w - m.w) * iv.w;
            }
            uint2 hv, lv;
            split4(v, hv, lv);
            uint32_t off = r256 + ((((c4 >> 3) ^ r7) << 4) | ((c4 & 7) << 1));
            *(uint2*)(Ahi + off) = hv;
            *(uint2*)(Alo + off) = lv;
        }
    }
}

// ---------------- PdPs ----------------
template<int NORM>
__global__ __launch_bounds__(512, 1)
void tc_pdps(const float* __restrict__ A0, const char* __restrict__ Wt,
             float* __restrict__ Pd, float* __restrict__ Ps,
             const float* __restrict__ accPrev) {
    extern __shared__ char dyn[];
    __shared__ float s_stats[256];
    const int tid = threadIdx.x;
    const int wid = tid >> 5;
    const int lid = tid & 31;
    const int m0  = blockIdx.x * 128;
    uint32_t dyn_u32 = smem_u32(dyn);
    uint32_t pad = ((dyn_u32 + 1023u) & ~1023u) - dyn_u32;
    char* tiles = dyn + pad;
    uint32_t tiles_u32 = dyn_u32 + pad;

    if (NORM) {
        compute_stats(accPrev, m0 >> 10, s_stats, tid);
        __syncthreads();
    }
    stage_rows<512, 128, NORM>(A0, m0, tiles, tiles + 32768, s_stats, tid);
    {
        const float4* wsrc = (const float4*)Wt;
        float4* wdst = (float4*)(tiles + 65536);
#pragma unroll
        for (int j = 0; j < 16; ++j)
            wdst[tid + j * 512] = wsrc[tid + j * 512];
    }
    __syncthreads();

    const int warp_m = wid & 3;
    const int warp_n = wid >> 2;
    const int quad = lid >> 3;
    const int lrow = lid & 7;
    const int a_rl = (quad & 1) * 8 + lrow;
    const int akq  = quad >> 1;
    const int b_rl = (quad >> 1) * 8 + lrow;
    const int bkq  = quad & 1;
    uint32_t arow256[2]; int ar7[2];
#pragma unroll
    for (int mt = 0; mt < 2; ++mt) {
        int rr = warp_m * 32 + mt * 16 + a_rl;
        arow256[mt] = (uint32_t)rr * 256; ar7[mt] = rr & 7;
    }
    uint32_t brow256[2]; int br7[2];
#pragma unroll
    for (int pj = 0; pj < 2; ++pj) {
        int rr = warp_n * 32 + pj * 16 + b_rl;
        brow256[pj] = (uint32_t)rr * 256; br7[pj] = rr & 7;
    }
    const int gr = lid >> 2;
    const int gc = (lid & 3) << 1;

#pragma unroll
    for (int h2 = 0; h2 < 2; ++h2) {
        const uint32_t wb = tiles_u32 + 65536 + (uint32_t)h2 * 65536;
        float c[2][4][4];
#pragma unroll
        for (int mt = 0; mt < 2; ++mt)
#pragma unroll
            for (int nt = 0; nt < 4; ++nt)
#pragma unroll
                for (int i = 0; i < 4; ++i) c[mt][nt][i] = 0.f;

#pragma unroll
        for (int ks = 0; ks < 8; ++ks) {
            const int kb = ks * 2;
            uint32_t ahi[2][4], alo[2][4], bhi[2][4], blo[2][4];
#pragma unroll
            for (int mt = 0; mt < 2; ++mt) {
                uint32_t sw = (uint32_t)(((kb + akq) ^ ar7[mt]) << 4);
                ldmx4(ahi[mt], tiles_u32 + arow256[mt] + sw);
                ldmx4(alo[mt], tiles_u32 + 32768 + arow256[mt] + sw);
            }
#pragma unroll
            for (int pj = 0; pj < 2; ++pj) {
                uint32_t swb = (uint32_t)(((kb + bkq) ^ br7[pj]) << 4);
                ldmx4(bhi[pj], wb + brow256[pj] + swb);
                ldmx4(blo[pj], wb + 32768 + brow256[pj] + swb);
            }
#pragma unroll
            for (int mt = 0; mt < 2; ++mt)
#pragma unroll
                for (int nt = 0; nt < 4; ++nt) {
                    const uint32_t* bh = &bhi[nt >> 1][(nt & 1) * 2];
                    const uint32_t* bl = &blo[nt >> 1][(nt & 1) * 2];
                    mma16816(c[mt][nt], ahi[mt], bh);
                    mma16816(c[mt][nt], ahi[mt], bl);
                    mma16816(c[mt][nt], alo[mt], bh);
                }
        }

        float* C = h2 ? Ps : Pd;
#pragma unroll
        for (int mt = 0; mt < 2; ++mt) {
            int mrow = m0 + warp_m * 32 + mt * 16 + gr;
#pragma unroll
            for (int nt = 0; nt < 4; ++nt) {
                int n = warp_n * 32 + nt * 8 + gc;
                *(float2*)(C + (size_t)mrow * 128 + n) =
                    make_float2(c[mt][nt][0], c[mt][nt][1]);
                *(float2*)(C + (size_t)(mrow + 8) * 128 + n) =
                    make_float2(c[mt][nt][2], c[mt][nt][3]);
            }
        }
    }
}

// ---------------- edge GEMM: persistent, warp-specialized (R12 proven form) ----------------
__global__ __launch_bounds__(512, 1)
void tc_edge(const float* __restrict__ Pd, const float* __restrict__ Ps,
             const char* __restrict__ Wt,
             const float* __restrict__ preBias, const float* __restrict__ postBias,
             float* __restrict__ C,
             const int* __restrict__ dstIdx, const int* __restrict__ srcIdx,
             float* __restrict__ zeroAcc) {
    extern __shared__ char dyn[];
    const int tid = threadIdx.x;
    const int wid = tid >> 5;
    const int lid = tid & 31;
    uint32_t dyn_u32 = smem_u32(dyn);
    uint32_t pad = ((dyn_u32 + 1023u) & ~1023u) - dyn_u32;
    char* tiles = dyn + pad;
    uint32_t tiles_u32 = dyn_u32 + pad;
    // buf0 @0 (hi 32K, lo @32K), buf1 @64K, W @128K (hi, lo @+32K)

    if (zeroAcc && blockIdx.x == 0) {
        ((float4*)zeroAcc)[tid] = make_float4(0.f, 0.f, 0.f, 0.f);
        ((float4*)zeroAcc)[tid + 512] = make_float4(0.f, 0.f, 0.f, 0.f);
    }
    {
        const float4* wsrc = (const float4*)Wt;
        float4* wdst = (float4*)(tiles + 131072);
#pragma unroll
        for (int j = 0; j < 8; ++j)
            wdst[tid + j * 512] = wsrc[tid + j * 512];
    }
    __syncthreads();

    const int grid = gridDim.x;
    const int NT = N_EDGES / 128;

    if (wid >= 8) {
        // ---------------- producer (coalesced, indices prefetched) ----------------
        const int pw   = wid - 8;
        const int esub = lid >> 3;
        const int ch8  = lid & 7;
        float4 bias4[4];
#pragma unroll
        for (int cg = 0; cg < 4; ++cg)
            bias4[cg] = *(const float4*)(preBias + (ch8 + cg * 8) * 4);
        int i = 0;
        for (int tile = blockIdx.x; tile < NT; tile += grid, ++i) {
            int b = i & 1;
            int di[4], si[4];
#pragma unroll
            for (int eg = 0; eg < 4; ++eg) {
                const int e = tile * 128 + pw * 16 + eg * 4 + esub;
                di[eg] = dstIdx[e];
                si[eg] = srcIdx[e];
            }
            if (i >= 2) BAR_SYNC(3 + b);
            char* Ah = tiles + b * 65536;
            char* Al = Ah + 32768;
#pragma unroll
            for (int eg = 0; eg < 4; ++eg) {
                const int elocal = pw * 16 + eg * 4 + esub;
                const float* pd = Pd + (size_t)di[eg] * 128;
                const float* ps = Ps + (size_t)si[eg] * 128;
                const int r7 = elocal & 7;
                const uint32_t r256 = (uint32_t)elocal * 256;
#pragma unroll
                for (int cg = 0; cg < 4; ++cg) {
                    const int c4 = (ch8 + cg * 8) * 4;
                    float4 a  = *(const float4*)(pd + c4);
                    float4 s  = *(const float4*)(ps + c4);
                    float4 v;
                    v.x = fmaxf(a.x + s.x + bias4[cg].x, 0.f);
                    v.y = fmaxf(a.y + s.y + bias4[cg].y, 0.f);
                    v.z = fmaxf(a.z + s.z + bias4[cg].z, 0.f);
                    v.w = fmaxf(a.w + s.w + bias4[cg].w, 0.f);
                    uint2 hv, lv;
                    split4(v, hv, lv);
                    uint32_t off = r256 + ((((c4 >> 3) ^ r7) << 4) | ((c4 & 7) << 1));
                    *(uint2*)(Ah + off) = hv;
                    *(uint2*)(Al + off) = lv;
                }
            }
            __threadfence_block();
            BAR_ARRIVE(1 + b);
        }
    } else {
        // ---------------- consumer ----------------
        const int warp_m = wid & 3;
        const int warp_n = wid >> 2;
        const int quad = lid >> 3;
        const int lrow = lid & 7;
        const int a_rl = (quad & 1) * 8 + lrow;
        const int akq  = quad >> 1;
        const int b_rl = (quad >> 1) * 8 + lrow;
        const int bkq  = quad & 1;
        uint32_t arow256[2]; int ar7[2];
#pragma unroll
        for (int mt = 0; mt < 2; ++mt) {
            int rr = warp_m * 32 + mt * 16 + a_rl;
            arow256[mt] = (uint32_t)rr * 256; ar7[mt] = rr & 7;
        }
        uint32_t brow256[4]; int br7[4];
#pragma unroll
        for (int pj = 0; pj < 4; ++pj) {
            int rr = warp_n * 64 + pj * 16 + b_rl;
            brow256[pj] = (uint32_t)rr * 256; br7[pj] = rr & 7;
        }
        const int gr = lid >> 2;
        const int gc = (lid & 3) << 1;
        float2 pbr[8];
#pragma unroll
        for (int nt = 0; nt < 8; ++nt)
            pbr[nt] = *(const float2*)(postBias + warp_n * 64 + nt * 8 + gc);

        int i = 0;
        for (int tile = blockIdx.x; tile < NT; tile += grid, ++i) {
            int b = i & 1;
            BAR_SYNC(1 + b);
            uint32_t Abase = tiles_u32 + b * 65536;

            // prefetch epilogue scatter indices (latency hides under MMA loop)
            int d0r[2], d1r[2];
#pragma unroll
            for (int mt = 0; mt < 2; ++mt) {
                int mrow = tile * 128 + warp_m * 32 + mt * 16 + gr;
                d0r[mt] = dstIdx[mrow];
                d1r[mt] = dstIdx[mrow + 8];
            }

            float c[2][8][4];
#pragma unroll
            for (int mt = 0; mt < 2; ++mt)
#pragma unroll
                for (int nt = 0; nt < 8; ++nt)
#pragma unroll
                    for (int k = 0; k < 4; ++k) c[mt][nt][k] = 0.f;

#pragma unroll
            for (int ks = 0; ks < 8; ++ks) {
                const int kb = ks * 2;
                uint32_t ahi[2][4], alo[2][4];
#pragma unroll
                for (int mt = 0; mt < 2; ++mt) {
                    uint32_t sw = (uint32_t)(((kb + akq) ^ ar7[mt]) << 4);
                    ldmx4(ahi[mt], Abase + arow256[mt] + sw);
                    ldmx4(alo[mt], Abase + 32768 + arow256[mt] + sw);
                }
#pragma unroll
                for (int pj = 0; pj < 4; ++pj) {
                    uint32_t bh[4], bl[4];
                    uint32_t swb = (uint32_t)(((kb + bkq) ^ br7[pj]) << 4);
                    ldmx4(bh, tiles_u32 + 131072 + brow256[pj] + swb);
                    ldmx4(bl, tiles_u32 + 163840 + brow256[pj] + swb);
#pragma unroll
                    for (int mt = 0; mt < 2; ++mt)
#pragma unroll
                        for (int sub = 0; sub < 2; ++sub) {
                            float* cc = c[mt][pj * 2 + sub];
                            mma16816(cc, ahi[mt], bh + sub * 2);
                            mma16816(cc, ahi[mt], bl + sub * 2);
                            mma16816(cc, alo[mt], bh + sub * 2);
                        }
                }
            }
            BAR_ARRIVE(3 + b);

#pragma unroll
            for (int mt = 0; mt < 2; ++mt) {
                const int d0 = d0r[mt];
                const int d1 = d1r[mt];
#pragma unroll
                for (int nt = 0; nt < 8; ++nt) {
                    int n = warp_n * 64 + nt * 8 + gc;
                    float o0 = fmaxf(c[mt][nt][0] + pbr[nt].x, 0.f);
                    float o1 = fmaxf(c[mt][nt][1] + pbr[nt].y, 0.f);
                    float o2 = fmaxf(c[mt][nt][2] + pbr[nt].x, 0.f);
                    float o3 = fmaxf(c[mt][nt][3] + pbr[nt].y, 0.f);
                    if (o0 != 0.f || o1 != 0.f) red_add_v2(C + (size_t)d0 * 128 + n, o0, o1);
                    if (o2 != 0.f || o3 != 0.f) red_add_v2(C + (size_t)d1 * 128 + n, o2, o3);
                }
            }
        }
    }
}

// ---------------- fused U1+U2 ----------------
template<int NORM>
__global__ __launch_bounds__(512, 1)
void tc_u1u2(const float* __restrict__ A0, const float* __restrict__ A1,
             const char* __restrict__ Wt1, const float* __restrict__ BU1,
             const char* __restrict__ Wt2, const float* __restrict__ BU2,
             float* __restrict__ C2, const float* __restrict__ accPrev,
             float* __restrict__ accCur, float* __restrict__ aggNext) {
    extern __shared__ char dyn[];
    __shared__ float s_stats[256];
    const int tid = threadIdx.x;
    const int wid = tid >> 5;
    const int lid = tid & 31;
    const int m0  = blockIdx.x * 128;
    uint32_t dyn_u32 = smem_u32(dyn);
    uint32_t pad = ((dyn_u32 + 1023u) & ~1023u) - dyn_u32;
    char* tiles = dyn + pad;
    uint32_t tiles_u32 = dyn_u32 + pad;

    const int warp_m = wid & 3;
    const int warp_n = wid >> 2;
    const int quad = lid >> 3;
    const int lrow = lid & 7;
    const int a_rl = (quad & 1) * 8 + lrow;
    const int akq  = quad >> 1;
    const int b_rl = (quad >> 1) * 8 + lrow;
    const int bkq  = quad & 1;
    uint32_t arow256[2]; int ar7[2];
#pragma unroll
    for (int mt = 0; mt < 2; ++mt) {
        int rr = warp_m * 32 + mt * 16 + a_rl;
        arow256[mt] = (uint32_t)rr * 256; ar7[mt] = rr & 7;
    }
    uint32_t brow256[2]; int br7[2];
#pragma unroll
    for (int pj = 0; pj < 2; ++pj) {
        int rr = warp_n * 32 + pj * 16 + b_rl;
        brow256[pj] = (uint32_t)rr * 256; br7[pj] = rr & 7;
    }
    const int gr = lid >> 2;
    const int gc = (lid & 3) << 1;

    if (NORM) {
        compute_stats(accPrev, m0 >> 10, s_stats, tid);
        __syncthreads();
    }

    // ======== U1 ========
    float c[2][4][4];
#pragma unroll
    for (int mt = 0; mt < 2; ++mt)
#pragma unroll
        for (int nt = 0; nt < 4; ++nt)
#pragma unroll
            for (int i = 0; i < 4; ++i) c[mt][nt][i] = 0.f;

    for (int p = 0; p < 2; ++p) {
        if (p) __syncthreads();
        if (p == 0)
            stage_rows<512, 128, NORM>(A0, m0, tiles, tiles + 32768, s_stats, tid);
        else {
            stage_rows<512, 128, 0>(A1, m0, tiles, tiles + 32768, nullptr, tid);
            const int sr = tid >> 3, ch8 = tid & 7;
#pragma unroll
            for (int pass = 0; pass < 2; ++pass) {
                int node = m0 + sr + pass * 64;
                float4* zr = (float4*)(aggNext + (size_t)node * 128) + ch8;
#pragma unroll
                for (int j = 0; j < 4; ++j)
                    zr[j * 8] = make_float4(0.f, 0.f, 0.f, 0.f);
            }
        }
        {
            const float4* wsrc = (const float4*)(Wt1 + (size_t)p * 65536);
            float4* wdst = (float4*)(tiles + 65536);
#pragma unroll
            for (int j = 0; j < 8; ++j)
                wdst[tid + j * 512] = wsrc[tid + j * 512];
        }
        __syncthreads();

#pragma unroll
        for (int ks = 0; ks < 8; ++ks) {
            const int kb = ks * 2;
            uint32_t ahi[2][4], alo[2][4], bhi[2][4], blo[2][4];
#pragma unroll
            for (int mt = 0; mt < 2; ++mt) {
                uint32_t sw = (uint32_t)(((kb + akq) ^ ar7[mt]) << 4);
                ldmx4(ahi[mt], tiles_u32 + arow256[mt] + sw);
                ldmx4(alo[mt], tiles_u32 + 32768 + arow256[mt] + sw);
            }
#pragma unroll
            for (int pj = 0; pj < 2; ++pj) {
                uint32_t swb = (uint32_t)(((kb + bkq) ^ br7[pj]) << 4);
                ldmx4(bhi[pj], tiles_u32 + 65536 + brow256[pj] + swb);
                ldmx4(blo[pj], tiles_u32 + 98304 + brow256[pj] + swb);
            }
#pragma unroll
            for (int mt = 0; mt < 2; ++mt)
#pragma unroll
                for (int nt = 0; nt < 4; ++nt) {
                    const uint32_t* bh = &bhi[nt >> 1][(nt & 1) * 2];
                    const uint32_t* bl = &blo[nt >> 1][(nt & 1) * 2];
                    mma16816(c[mt][nt], ahi[mt], bh);
                    mma16816(c[mt][nt], ahi[mt], bl);
                    mma16816(c[mt][nt], alo[mt], bh);
                }
        }
    }

    // ======== U1 epilogue -> smem bf16 t1 tile ========
    __syncthreads();
#pragma unroll
    for (int mt = 0; mt < 2; ++mt) {
        const int r1 = warp_m * 32 + mt * 16 + gr;
        const int r2 = r1 + 8;
#pragma unroll
        for (int nt = 0; nt < 4; ++nt) {
            const int n = warp_n * 32 + nt * 8 + gc;
            float2 pb = *(const float2*)(BU1 + n);
            float o0 = fmaxf(c[mt][nt][0] + pb.x, 0.f);
            float o1 = fmaxf(c[mt][nt][1] + pb.y, 0.f);
            float o2 = fmaxf(c[mt][nt][2] + pb.x, 0.f);
            float o3 = fmaxf(c[mt][nt][3] + pb.y, 0.f);
            uint32_t hv, lv;
            split2(o0, o1, hv, lv);
            uint32_t off1 = (uint32_t)(r1 * 256 + ((((n >> 3) ^ (r1 & 7)) << 4) | ((n & 7) << 1)));
            *(uint32_t*)(tiles + off1) = hv;
            *(uint32_t*)(tiles + 32768 + off1) = lv;
            split2(o2, o3, hv, lv);
            uint32_t off2 = (uint32_t)(r2 * 256 + ((((n >> 3) ^ (r2 & 7)) << 4) | ((n & 7) << 1)));
            *(uint32_t*)(tiles + off2) = hv;
            *(uint32_t*)(tiles + 32768 + off2) = lv;
        }
    }
    {
        const float4* wsrc = (const float4*)Wt2;
        float4* wdst = (float4*)(tiles + 65536);
#pragma unroll
        for (int j = 0; j < 8; ++j)
            wdst[tid + j * 512] = wsrc[tid + j * 512];
    }
    __syncthreads();

    // ======== U2 ========
    float c2[2][4][4];
#pragma unroll
    for (int mt = 0; mt < 2; ++mt)
#pragma unroll
        for (int nt = 0; nt < 4; ++nt)
#pragma unroll
            for (int i = 0; i < 4; ++i) c2[mt][nt][i] = 0.f;

#pragma unroll
    for (int ks = 0; ks < 8; ++ks) {
        const int kb = ks * 2;
        uint32_t ahi[2][4], alo[2][4], bhi[2][4], blo[2][4];
#pragma unroll
        for (int mt = 0; mt < 2; ++mt) {
            uint32_t sw = (uint32_t)(((kb + akq) ^ ar7[mt]) << 4);
            ldmx4(ahi[mt], tiles_u32 + arow256[mt] + sw);
            ldmx4(alo[mt], tiles_u32 + 32768 + arow256[mt] + sw);
        }
#pragma unroll
        for (int pj = 0; pj < 2; ++pj) {
            uint32_t swb = (uint32_t)(((kb + bkq) ^ br7[pj]) << 4);
            ldmx4(bhi[pj], tiles_u32 + 65536 + brow256[pj] + swb);
            ldmx4(blo[pj], tiles_u32 + 98304 + brow256[pj] + swb);
        }
#pragma unroll
        for (int mt = 0; mt < 2; ++mt)
#pragma unroll
            for (int nt = 0; nt < 4; ++nt) {
                const uint32_t* bh = &bhi[nt >> 1][(nt & 1) * 2];
                const uint32_t* bl = &blo[nt >> 1][(nt & 1) * 2];
                mma16816(c2[mt][nt], ahi[mt], bh);
                mma16816(c2[mt][nt], ahi[mt], bl);
                mma16816(c2[mt][nt], alo[mt], bh);
            }
    }

    // ======== U2 epilogue ========
    const int batch = m0 >> 10;
    float* accS = accCur + batch * 128;
    float* accQ = accCur + NBATCH * NHID + batch * 128;
#pragma unroll
    for (int nt = 0; nt < 4; ++nt) {
        const int n = warp_n * 32 + nt * 8 + gc;
        float2 pb = *(const float2*)(BU2 + n);
        float s0 = 0.f, s1 = 0.f, q0 = 0.f, q1 = 0.f;
#pragma unroll
        for (int mt = 0; mt < 2; ++mt) {
            int mrow = m0 + warp_m * 32 + mt * 16 + gr;
            float o0 = fmaxf(c2[mt][nt][0] + pb.x, 0.f);
            float o1 = fmaxf(c2[mt][nt][1] + pb.y, 0.f);
            float o2 = fmaxf(c2[mt][nt][2] + pb.x, 0.f);
            float o3 = fmaxf(c2[mt][nt][3] + pb.y, 0.f);
            *(float2*)(C2 + (size_t)mrow * 128 + n)       = make_float2(o0, o1);
            *(float2*)(C2 + (size_t)(mrow + 8) * 128 + n) = make_float2(o2, o3);
            s0 += o0 + o2;
            s1 += o1 + o3;
            q0 += o0 * o0 + o2 * o2;
            q1 += o1 * o1 + o3 * o3;
        }
#pragma unroll
        for (int off = 4; off < 32; off <<= 1) {
            s0 += __shfl_xor_sync(0xFFFFFFFFu, s0, off);
            s1 += __shfl_xor_sync(0xFFFFFFFFu, s1, off);
            q0 += __shfl_xor_sync(0xFFFFFFFFu, q0, off);
            q1 += __shfl_xor_sync(0xFFFFFFFFu, q1, off);
        }
        if (lid < 4) {
            red_add_v2(accS + n, s0, s1);
            red_add_v2(accQ + n, q0, q1);
        }
    }
}

// ---------------- decoder / discrepancy / final ----------------
__global__ void decoder_kernel(const float* __restrict__ H,
                               const float* __restrict__ acc,
                               const float* __restrict__ W,
                               const float* __restrict__ B,
                               float* __restrict__ GX,
                               float* __restrict__ x_out) {
    int gthread = blockIdx.x * blockDim.x + threadIdx.x;
    int n = gthread >> 5;
    int lane = threadIdx.x & 31;
    if (n >= N_NODES) return;
    const float* hr = H + (size_t)n * 128;
    const float* accS = acc + (n >> 10) * 128;
    const float* accQ = accS + NBATCH * NHID;
    float a0 = 0.f, a1 = 0.f, a2 = 0.f, a3 = 0.f;
#pragma unroll
    for (int k = 0; k < 128; k += 32) {
        float s = accS[k + lane];
        float q = accQ[k + lane];
        float mean = s * (1.0f / NSAMPLES);
        float var = q * (1.0f / NSAMPLES) - mean * mean;
        float hv = (hr[k + lane] - mean) * rsqrtf(var + EPSV);
        float4 w = ((const float4*)W)[k + lane];
        a0 += hv * w.x;
        a1 += hv * w.y;
        a2 += hv * w.z;
        a3 += hv * w.w;
    }
#pragma unroll
    for (int off = 16; off > 0; off >>= 1) {
        a0 += __shfl_xor_sync(0xFFFFFFFFu, a0, off);
        a1 += __shfl_xor_sync(0xFFFFFFFFu, a1, off);
        a2 += __shfl_xor_sync(0xFFFFFFFFu, a2, off);
        a3 += __shfl_xor_sync(0xFFFFFFFFu, a3, off);
    }
    if (lane == 0) {
        float z0 = 1.f / (1.f + expf(-(a0 + B[0])));
        float z1 = 1.f / (1.f + expf(-(a1 + B[1])));
        float z2 = 1.f / (1.f + expf(-(a2 + B[2])));
        float z3 = 1.f / (1.f + expf(-(a3 + B[3])));
        ((float4*)GX)[n] = make_float4(z0, z1, z2, z3);
        if (x_out) {
            x_out[n * 4 + 0] = z0;
            x_out[n * 4 + 1] = z1;
            x_out[n * 4 + 2] = z2;
            x_out[n * 4 + 3] = z3;
        }
    }
}

__global__ void disc_kernel(const float* __restrict__ GX) {
    __shared__ float4 sx[NSAMPLES];
    __shared__ float red1[128];
    __shared__ float red2[128];
    int b = blockIdx.x;
    int chunk = blockIdx.y;
    int tid = threadIdx.x;
    const float4* xb = (const float4*)GX + (size_t)b * NSAMPLES;
    for (int i = tid; i < NSAMPLES; i += 128) sx[i] = xb[i];
    __syncthreads();
    int i = chunk * 128 + tid;
    float4 xi = sx[i];
    float p1 = (1.f - xi.x * xi.x) * (1.f - xi.y * xi.y) *
               (1.f - xi.z * xi.z) * (1.f - xi.w * xi.w);
    float s2a = 0.f, s2b = 0.f, s2c = 0.f, s2d = 0.f;
#pragma unroll 2
    for (int j = 0; j < NSAMPLES; j += 4) {
        float4 x0 = sx[j];
        float4 x1 = sx[j + 1];
        float4 x2 = sx[j + 2];
        float4 x3 = sx[j + 3];
        s2a += (1.f - fmaxf(xi.x, x0.x)) * (1.f - fmaxf(xi.y, x0.y)) *
               (1.f - fmaxf(xi.z, x0.z)) * (1.f - fmaxf(xi.w, x0.w));
        s2b += (1.f - fmaxf(xi.x, x1.x)) * (1.f - fmaxf(xi.y, x1.y)) *
               (1.f - fmaxf(xi.z, x1.z)) * (1.f - fmaxf(xi.w, x1.w));
        s2c += (1.f - fmaxf(xi.x, x2.x)) * (1.f - fmaxf(xi.y, x2.y)) *
               (1.f - fmaxf(xi.z, x2.z)) * (1.f - fmaxf(xi.w, x2.w));
        s2d += (1.f - fmaxf(xi.x, x3.x)) * (1.f - fmaxf(xi.y, x3.y)) *
               (1.f - fmaxf(xi.z, x3.z)) * (1.f - fmaxf(xi.w, x3.w));
    }
    float s2 = (s2a + s2b) + (s2c + s2d);
    red1[tid] = p1;
    red2[tid] = s2;
    __syncthreads();
    for (int s = 64; s > 0; s >>= 1) {
        if (tid < s) {
            red1[tid] += red1[tid + s];
            red2[tid] += red2[tid + s];
        }
        __syncthreads();
    }
    if (tid == 0) {
        atomicAdd(&g_dsum[b], red1[0]);
        atomicAdd(&g_dsum[16 + b], red2[0]);
    }
}

__global__ void final_kernel(float* __restrict__ loss_out) {
    if (threadIdx.x == 0 && blockIdx.x == 0) {
        float acc = 0.f;
        const float invN = 1.0f / (float)NSAMPLES;
        for (int b = 0; b < NBATCH; ++b) {
            float s1 = g_dsum[b];
            float s2 = g_dsum[16 + b];
            float v = (1.0f / 81.0f) - invN * 0.125f * s1 + s2 * invN * invN;
            acc += sqrtf(v);
        }
        float loss = acc / (float)NBATCH;
        if (loss_out) *loss_out = loss;
    }
}

// ---------------- launch ----------------
extern "C" void kernel_launch(void* const* d_in, const int* in_sizes, int n_in,
                              void* d_out, int out_size) {
    const float *X, *enc_w, *enc_b, *dec_w, *dec_b;
    const float *m1w, *m1b, *m2w, *m2b, *u1w, *u1b, *u2w, *u2b;
    const int* ei = (const int*)d_in[1];
    X = (const float*)d_in[0];
    bool dictOrder = (in_sizes[5] == 512);
    if (dictOrder) {
        enc_w = (const float*)d_in[3];  enc_b = (const float*)d_in[4];
        dec_w = (const float*)d_in[5];  dec_b = (const float*)d_in[6];
        m1w = (const float*)d_in[7];    m1b = (const float*)d_in[8];
        m2w = (const float*)d_in[9];    m2b = (const float*)d_in[10];
        u1w = (const float*)d_in[11];   u1b = (const float*)d_in[12];
        u2w = (const float*)d_in[13];   u2b = (const float*)d_in[14];
    } else {
        enc_w = (const float*)d_in[3];  enc_b = (const float*)d_in[4];
        m1w = (const float*)d_in[5];    m1b = (const float*)d_in[6];
        m2w = (const float*)d_in[7];    m2b = (const float*)d_in[8];
        u1w = (const float*)d_in[9];    u1b = (const float*)d_in[10];
        u2w = (const float*)d_in[11];   u2b = (const float*)d_in[12];
        dec_w = (const float*)d_in[13]; dec_b = (const float*)d_in[14];
    }
    const int* src = ei;
    const int* dst = ei + N_EDGES;

    void* p;
    float *h_, *Pd, *Ps, *aggA, *aggB, *t2, *gx, *naccA, *naccB;
    char* wt;
    cudaGetSymbolAddress(&p, g_h);      h_   = (float*)p;
    cudaGetSymbolAddress(&p, g_Pd);     Pd   = (float*)p;
    cudaGetSymbolAddress(&p, g_Ps);     Ps   = (float*)p;
    cudaGetSymbolAddress(&p, g_agg);    aggA = (float*)p;
    cudaGetSymbolAddress(&p, g_agg2);   aggB = (float*)p;
    cudaGetSymbolAddress(&p, g_t2);     t2   = (float*)p;
    cudaGetSymbolAddress(&p, g_x);      gx   = (float*)p;
    cudaGetSymbolAddress(&p, g_naccA);  naccA = (float*)p;
    cudaGetSymbolAddress(&p, g_naccB);  naccB = (float*)p;
    cudaGetSymbolAddress(&p, g_wt);     wt   = (char*)p;
    float* aggs[2]  = {aggA, aggB};
    float* naccs[2] = {naccA, naccB};

    float* out = (float*)d_out;
    float* loss_out;
    float* x_out;
    if (out_size >= N_NODES * DIMX + 1) { loss_out = out; x_out = out + 1; }
    else if (out_size == N_NODES * DIMX) { loss_out = nullptr; x_out = out; }
    else { loss_out = out; x_out = nullptr; }

    cudaFuncSetAttribute(tc_pdps<0>, cudaFuncAttributeMaxDynamicSharedMemorySize, PDPS_SMEM);
    cudaFuncSetAttribute(tc_pdps<1>, cudaFuncAttributeMaxDynamicSharedMemorySize, PDPS_SMEM);
    cudaFuncSetAttribute(tc_edge,    cudaFuncAttributeMaxDynamicSharedMemorySize, EDGE_SMEM);
    cudaFuncSetAttribute(tc_u1u2<0>, cudaFuncAttributeMaxDynamicSharedMemorySize, U1_SMEM);
    cudaFuncSetAttribute(tc_u1u2<1>, cudaFuncAttributeMaxDynamicSharedMemorySize, U1_SMEM);

    // ---- weight prep ----
    PrepJobs jobs;
    for (int l = 0; l < NLAYERS; ++l) {
        char* lb = wt + (size_t)l * WT_LAYER_STRIDE;
        jobs.src[l*5+0] = m1w + (size_t)l * 256 * 128;            jobs.dst[l*5+0] = lb + WT_W1A; jobs.nelem[l*5+0] = 128*128;
        jobs.src[l*5+1] = m1w + (size_t)l * 256 * 128 + 128*128;  jobs.dst[l*5+1] = lb + WT_W1B; jobs.nelem[l*5+1] = 128*128;
        jobs.src[l*5+2] = m2w + (size_t)l * 128 * 128;            jobs.dst[l*5+2] = lb + WT_W2;  jobs.nelem[l*5+2] = 128*128;
        jobs.src[l*5+3] = u1w + (size_t)l * 256 * 128;            jobs.dst[l*5+3] = lb + WT_U1;  jobs.nelem[l*5+3] = 256*128;
        jobs.src[l*5+4] = u2w + (size_t)l * 128 * 128;            jobs.dst[l*5+4] = lb + WT_U2;  jobs.nelem[l*5+4] = 128*128;
    }
    prep_w_all<<<dim3(128, 15), 256>>>(jobs);

    encoder_kernel<<<(N_NODES * NHID) / 256, 256>>>(X, enc_w, enc_b, h_);

    for (int l = 0; l < NLAYERS; ++l) {
        char* lb = wt + (size_t)l * WT_LAYER_STRIDE;
        const float* B1  = m1b + l * 128;
        const float* B2  = m2b + l * 128;
        const float* BU1 = u1b + l * 128;
        const float* BU2 = u2b + l * 128;
        const float* Aprev = (l == 0) ? h_ : t2;
        float* aggCur  = aggs[l & 1];
        float* aggNext = aggs[(l + 1) & 1];
        float* accPrev = (l == 0) ? nullptr : naccs[(l - 1) & 1];
        float* accCur  = naccs[l & 1];
        float* zeroAcc = (l == 2) ? accCur : nullptr;

        if (l == 0)
            tc_pdps<0><<<128, 512, PDPS_SMEM>>>(Aprev, lb + WT_W1A, Pd, Ps, nullptr);
        else
            tc_pdps<1><<<128, 512, PDPS_SMEM>>>(Aprev, lb + WT_W1A, Pd, Ps, accPrev);

        tc_edge<<<148, 512, EDGE_SMEM>>>(Pd, Ps, lb + WT_W2, B1, B2, aggCur, dst, src, zeroAcc);

        if (l == 0)
            tc_u1u2<0><<<128, 512, U1_SMEM>>>(Aprev, aggCur, lb + WT_U1, BU1,
                                              lb + WT_U2, BU2, t2, nullptr, accCur, aggNext);
        else
            tc_u1u2<1><<<128, 512, U1_SMEM>>>(Aprev, aggCur, lb + WT_U1, BU1,
                                              lb + WT_U2, BU2, t2, accPrev, accCur, aggNext);
    }

    decoder_kernel<<<(N_NODES * 32) / 256, 256>>>(t2, naccs[(NLAYERS - 1) & 1],
                                                  dec_w, dec_b, gx, x_out);
    disc_kernel<<<dim3(NBATCH, 8), 128>>>(gx);
    final_kernel<<<1, 1>>>(loss_out);
}

// round 15
// speedup vs baseline: 1.0736x; 1.0098x over previous
#include <cuda_runtime.h>
#include <cuda_bf16.h>
#include <math.h>
#include <stdint.h>

// ---------------- problem constants ----------------
#define N_NODES   16384
#define N_EDGES   262144
#define NHID      128
#define NLAYERS   3
#define NBATCH    16
#define NSAMPLES  1024
#define DIMX      4
#define EPSV      1e-5f

#define WT_LAYER_STRIDE 393216
#define WT_W1A 0
#define WT_W1B 65536
#define WT_W2  131072
#define WT_U1  196608
#define WT_U2  327680

#define PDPS_SMEM  197632   // 1K pad + A 64K + W1a/W1b hi/lo 128K
#define EDGE_SMEM  197632   // 1K pad + 2 A bufs (2*64K) + W 64K
#define U1_SMEM    132096   // 1K pad + A 64K + W 64K

// ---------------- device scratch ----------------
__device__ float g_h [N_NODES * NHID];
__device__ float g_Pd[N_NODES * NHID];
__device__ float g_Ps[N_NODES * NHID];
__device__ float g_agg [N_NODES * NHID];
__device__ float g_agg2[N_NODES * NHID];
__device__ float g_t2[N_NODES * NHID];
__device__ float g_x [N_NODES * DIMX];
__device__ float g_naccA[2 * NBATCH * NHID];
__device__ float g_naccB[2 * NBATCH * NHID];
__device__ float g_dsum[32];
__device__ char  g_wt[NLAYERS * WT_LAYER_STRIDE];

// ---------------- helpers ----------------
__device__ __forceinline__ uint32_t smem_u32(const void* p) {
    uint32_t a;
    asm("{ .reg .u64 t; cvta.to.shared.u64 t, %1; cvt.u32.u64 %0, t; }" : "=r"(a) : "l"(p));
    return a;
}
__device__ __forceinline__ void red_add_v2(float* p, float a, float b) {
    asm volatile("red.global.add.v2.f32 [%0], {%1,%2};"
                 :: "l"(p), "f"(a), "f"(b) : "memory");
}
// packed cvt: returns {low = bf16(lo_), high = bf16(hi_)} — matches pack2(lo_, hi_)
__device__ __forceinline__ uint32_t cvt2bf(float hi_, float lo_) {
    uint32_t r;
    asm("cvt.rn.bf16x2.f32 %0, %1, %2;" : "=r"(r) : "f"(hi_), "f"(lo_));
    return r;
}
__device__ __forceinline__ void ldmx4(uint32_t* r, uint32_t addr) {
    asm volatile("ldmatrix.sync.aligned.m8n8.x4.shared.b16 {%0,%1,%2,%3}, [%4];"
                 : "=r"(r[0]), "=r"(r[1]), "=r"(r[2]), "=r"(r[3]) : "r"(addr));
}
__device__ __forceinline__ void mma16816(float* c, const uint32_t* a, const uint32_t* b) {
    asm volatile("mma.sync.aligned.m16n8k16.row.col.f32.bf16.bf16.f32 "
                 "{%0,%1,%2,%3}, {%4,%5,%6,%7}, {%8,%9}, {%0,%1,%2,%3};"
                 : "+f"(c[0]), "+f"(c[1]), "+f"(c[2]), "+f"(c[3])
                 : "r"(a[0]), "r"(a[1]), "r"(a[2]), "r"(a[3]), "r"(b[0]), "r"(b[1]));
}
#define BAR_SYNC(id)   asm volatile("bar.sync %0, 512;"   :: "r"(id) : "memory")
#define BAR_ARRIVE(id) asm volatile("bar.arrive %0, 512;" :: "r"(id) : "memory")

// split a float pair (a low, b high) into bf16 hi/lo packed words via bf16x2 cvt.
// Rounding identical to __float2bfloat16 path: hi = rn(x); lo = rn(x - float(hi)).
__device__ __forceinline__ void split2(float a, float b, uint32_t& hv, uint32_t& lv) {
    hv = cvt2bf(b, a);
    float fa = __uint_as_float(hv << 16);
    float fb = __uint_as_float(hv & 0xFFFF0000u);
    lv = cvt2bf(b - fb, a - fa);
}
__device__ __forceinline__ void split4(float4 v, uint2& hv, uint2& lv) {
    split2(v.x, v.y, hv.x, lv.x);
    split2(v.z, v.w, hv.y, lv.y);
}

__device__ __forceinline__ void compute_stats(const float* __restrict__ acc,
                                              int batch, float* s_stats, int tid) {
    if (tid < 128) {
        float s = acc[batch * 128 + tid];
        float q = acc[NBATCH * NHID + batch * 128 + tid];
        float mean = s * (1.0f / NSAMPLES);
        float var = q * (1.0f / NSAMPLES) - mean * mean;
        s_stats[tid] = mean;
        s_stats[128 + tid] = rsqrtf(var + EPSV);
    }
}

// ---------------- weight prep ----------------
struct PrepJobs {
    const float* src[15];
    char* dst[15];
    int nelem[15];
};
__global__ void prep_w_all(PrepJobs jobs) {
    int m = blockIdx.y;
    int idx = blockIdx.x * 256 + threadIdx.x;
    if (idx >= jobs.nelem[m]) return;
    const float* W = jobs.src[m];
    char* out = jobs.dst[m];
    int k = idx >> 7, n = idx & 127;
    float w = W[idx];
    __nv_bfloat16 hi = __float2bfloat16(w);
    __nv_bfloat16 lo = __float2bfloat16(w - __bfloat162float(hi));
    int phase = k >> 7, kk = k & 127;
    uint32_t off = (uint32_t)(n * 256 + ((((kk >> 3) ^ (n & 7)) << 4) | ((kk & 7) << 1)));
    *(__nv_bfloat16*)(out + (size_t)phase * 65536 + off) = hi;
    *(__nv_bfloat16*)(out + (size_t)phase * 65536 + 32768 + off) = lo;
}

// ---------------- encoder ----------------
__global__ void encoder_kernel(const float* __restrict__ X,
                               const float* __restrict__ W,
                               const float* __restrict__ B,
                               float* __restrict__ H) {
    int idx = blockIdx.x * blockDim.x + threadIdx.x;
    int n = idx >> 7;
    int c = idx & 127;
    float4 xv = ((const float4*)X)[n];
    float v = B[c];
    v += xv.x * W[c];
    v += xv.y * W[128 + c];
    v += xv.z * W[256 + c];
    v += xv.w * W[384 + c];
    H[idx] = v;
    g_agg[idx] = 0.f;
    if (idx < 2 * NBATCH * NHID) { g_naccA[idx] = 0.f; g_naccB[idx] = 0.f; }
    if (idx < 32) g_dsum[idx] = 0.f;
}

// ---------------- coalesced staging ----------------
template<int NTHREADS, int NROWS, int NORM>
__device__ __forceinline__ void stage_rows(
    const float* __restrict__ Abase, int row0,
    char* __restrict__ Ahi, char* __restrict__ Alo,
    const float* __restrict__ stats, int tid)
{
    const int sr  = tid >> 3;
    const int ch8 = tid & 7;
    const int ROWS_PER_PASS = NTHREADS / 8;
    const int NPASS = NROWS / ROWS_PER_PASS;
#pragma unroll
    for (int pass = 0; pass < NPASS; ++pass) {
        const int r = sr + pass * ROWS_PER_PASS;
        const int node = row0 + r;
        const float* arow = Abase + (size_t)node * 128;
        const int r7 = r & 7;
        const uint32_t r256 = (uint32_t)r * 256;
#pragma unroll
        for (int j = 0; j < 4; ++j) {
            const int c4 = (ch8 + j * 8) * 4;
            float4 v = *(const float4*)(arow + c4);
            if (NORM) {
                float4 m  = *(const float4*)(stats + c4);
                float4 iv = *(const float4*)(stats + 128 + c4);
                v.x = (v.x - m.x) * iv.x;
                v.y = (v.y - m.y) * iv.y;
                v.z = (v.z - m.z) * iv.z;
                v.w = (v.w - m.w) * iv.w;
            }
            uint2 hv, lv;
            split4(v, hv, lv);
            uint32_t off = r256 + ((((c4 >> 3) ^ r7) << 4) | ((c4 & 7) << 1));
            *(uint2*)(Ahi + off) = hv;
            *(uint2*)(Alo + off) = lv;
        }
    }
}

// ---------------- PdPs ----------------
template<int NORM>
__global__ __launch_bounds__(512, 1)
void tc_pdps(const float* __restrict__ A0, const char* __restrict__ Wt,
             float* __restrict__ Pd, float* __restrict__ Ps,
             const float* __restrict__ accPrev) {
    extern __shared__ char dyn[];
    __shared__ float s_stats[256];
    const int tid = threadIdx.x;
    const int wid = tid >> 5;
    const int lid = tid & 31;
    const int m0  = blockIdx.x * 128;
    uint32_t dyn_u32 = smem_u32(dyn);
    uint32_t pad = ((dyn_u32 + 1023u) & ~1023u) - dyn_u32;
    char* tiles = dyn + pad;
    uint32_t tiles_u32 = dyn_u32 + pad;

    if (NORM) {
        compute_stats(accPrev, m0 >> 10, s_stats, tid);
        __syncthreads();
    }
    stage_rows<512, 128, NORM>(A0, m0, tiles, tiles + 32768, s_stats, tid);
    {
        const float4* wsrc = (const float4*)Wt;
        float4* wdst = (float4*)(tiles + 65536);
#pragma unroll
        for (int j = 0; j < 16; ++j)
            wdst[tid + j * 512] = wsrc[tid + j * 512];
    }
    __syncthreads();

    const int warp_m = wid & 3;
    const int warp_n = wid >> 2;
    const int quad = lid >> 3;
    const int lrow = lid & 7;
    const int a_rl = (quad & 1) * 8 + lrow;
    const int akq  = quad >> 1;
    const int b_rl = (quad >> 1) * 8 + lrow;
    const int bkq  = quad & 1;
    uint32_t arow256[2]; int ar7[2];
#pragma unroll
    for (int mt = 0; mt < 2; ++mt) {
        int rr = warp_m * 32 + mt * 16 + a_rl;
        arow256[mt] = (uint32_t)rr * 256; ar7[mt] = rr & 7;
    }
    uint32_t brow256[2]; int br7[2];
#pragma unroll
    for (int pj = 0; pj < 2; ++pj) {
        int rr = warp_n * 32 + pj * 16 + b_rl;
        brow256[pj] = (uint32_t)rr * 256; br7[pj] = rr & 7;
    }
    const int gr = lid >> 2;
    const int gc = (lid & 3) << 1;

#pragma unroll
    for (int h2 = 0; h2 < 2; ++h2) {
        const uint32_t wb = tiles_u32 + 65536 + (uint32_t)h2 * 65536;
        float c[2][4][4];
#pragma unroll
        for (int mt = 0; mt < 2; ++mt)
#pragma unroll
            for (int nt = 0; nt < 4; ++nt)
#pragma unroll
                for (int i = 0; i < 4; ++i) c[mt][nt][i] = 0.f;

#pragma unroll
        for (int ks = 0; ks < 8; ++ks) {
            const int kb = ks * 2;
            uint32_t ahi[2][4], alo[2][4], bhi[2][4], blo[2][4];
#pragma unroll
            for (int mt = 0; mt < 2; ++mt) {
                uint32_t sw = (uint32_t)(((kb + akq) ^ ar7[mt]) << 4);
                ldmx4(ahi[mt], tiles_u32 + arow256[mt] + sw);
                ldmx4(alo[mt], tiles_u32 + 32768 + arow256[mt] + sw);
            }
#pragma unroll
            for (int pj = 0; pj < 2; ++pj) {
                uint32_t swb = (uint32_t)(((kb + bkq) ^ br7[pj]) << 4);
                ldmx4(bhi[pj], wb + brow256[pj] + swb);
                ldmx4(blo[pj], wb + 32768 + brow256[pj] + swb);
            }
#pragma unroll
            for (int mt = 0; mt < 2; ++mt)
#pragma unroll
                for (int nt = 0; nt < 4; ++nt) {
                    const uint32_t* bh = &bhi[nt >> 1][(nt & 1) * 2];
                    const uint32_t* bl = &blo[nt >> 1][(nt & 1) * 2];
                    mma16816(c[mt][nt], ahi[mt], bh);
                    mma16816(c[mt][nt], ahi[mt], bl);
                    mma16816(c[mt][nt], alo[mt], bh);
                }
        }

        float* C = h2 ? Ps : Pd;
#pragma unroll
        for (int mt = 0; mt < 2; ++mt) {
            int mrow = m0 + warp_m * 32 + mt * 16 + gr;
#pragma unroll
            for (int nt = 0; nt < 4; ++nt) {
                int n = warp_n * 32 + nt * 8 + gc;
                *(float2*)(C + (size_t)mrow * 128 + n) =
                    make_float2(c[mt][nt][0], c[mt][nt][1]);
                *(float2*)(C + (size_t)(mrow + 8) * 128 + n) =
                    make_float2(c[mt][nt][2], c[mt][nt][3]);
            }
        }
    }
}

// ---------------- edge GEMM: persistent, warp-specialized (R12 proven form) ----------------
__global__ __launch_bounds__(512, 1)
void tc_edge(const float* __restrict__ Pd, const float* __restrict__ Ps,
             const char* __restrict__ Wt,
             const float* __restrict__ preBias, const float* __restrict__ postBias,
             float* __restrict__ C,
             const int* __restrict__ dstIdx, const int* __restrict__ srcIdx,
             float* __restrict__ zeroAcc) {
    extern __shared__ char dyn[];
    const int tid = threadIdx.x;
    const int wid = tid >> 5;
    const int lid = tid & 31;
    uint32_t dyn_u32 = smem_u32(dyn);
    uint32_t pad = ((dyn_u32 + 1023u) & ~1023u) - dyn_u32;
    char* tiles = dyn + pad;
    uint32_t tiles_u32 = dyn_u32 + pad;
    // buf0 @0 (hi 32K, lo @32K), buf1 @64K, W @128K (hi, lo @+32K)

    if (zeroAcc && blockIdx.x == 0) {
        ((float4*)zeroAcc)[tid] = make_float4(0.f, 0.f, 0.f, 0.f);
        ((float4*)zeroAcc)[tid + 512] = make_float4(0.f, 0.f, 0.f, 0.f);
    }
    {
        const float4* wsrc = (const float4*)Wt;
        float4* wdst = (float4*)(tiles + 131072);
#pragma unroll
        for (int j = 0; j < 8; ++j)
            wdst[tid + j * 512] = wsrc[tid + j * 512];
    }
    __syncthreads();

    const int grid = gridDim.x;
    const int NT = N_EDGES / 128;

    if (wid >= 8) {
        // ---------------- producer (coalesced, indices prefetched) ----------------
        const int pw   = wid - 8;
        const int esub = lid >> 3;
        const int ch8  = lid & 7;
        float4 bias4[4];
#pragma unroll
        for (int cg = 0; cg < 4; ++cg)
            bias4[cg] = *(const float4*)(preBias + (ch8 + cg * 8) * 4);
        int i = 0;
        for (int tile = blockIdx.x; tile < NT; tile += grid, ++i) {
            int b = i & 1;
            int di[4], si[4];
#pragma unroll
            for (int eg = 0; eg < 4; ++eg) {
                const int e = tile * 128 + pw * 16 + eg * 4 + esub;
                di[eg] = dstIdx[e];
                si[eg] = srcIdx[e];
            }
            if (i >= 2) BAR_SYNC(3 + b);
            char* Ah = tiles + b * 65536;
            char* Al = Ah + 32768;
#pragma unroll
            for (int eg = 0; eg < 4; ++eg) {
                const int elocal = pw * 16 + eg * 4 + esub;
                const float* pd = Pd + (size_t)di[eg] * 128;
                const float* ps = Ps + (size_t)si[eg] * 128;
                const int r7 = elocal & 7;
                const uint32_t r256 = (uint32_t)elocal * 256;
#pragma unroll
                for (int cg = 0; cg < 4; ++cg) {
                    const int c4 = (ch8 + cg * 8) * 4;
                    float4 a  = *(const float4*)(pd + c4);
                    float4 s  = *(const float4*)(ps + c4);
                    float4 v;
                    v.x = fmaxf(a.x + s.x + bias4[cg].x, 0.f);
                    v.y = fmaxf(a.y + s.y + bias4[cg].y, 0.f);
                    v.z = fmaxf(a.z + s.z + bias4[cg].z, 0.f);
                    v.w = fmaxf(a.w + s.w + bias4[cg].w, 0.f);
                    uint2 hv, lv;
                    split4(v, hv, lv);
                    uint32_t off = r256 + ((((c4 >> 3) ^ r7) << 4) | ((c4 & 7) << 1));
                    *(uint2*)(Ah + off) = hv;
                    *(uint2*)(Al + off) = lv;
                }
            }
            __threadfence_block();
            BAR_ARRIVE(1 + b);
        }
    } else {
        // ---------------- consumer ----------------
        const int warp_m = wid & 3;
        const int warp_n = wid >> 2;
        const int quad = lid >> 3;
        const int lrow = lid & 7;
        const int a_rl = (quad & 1) * 8 + lrow;
        const int akq  = quad >> 1;
        const int b_rl = (quad >> 1) * 8 + lrow;
        const int bkq  = quad & 1;
        uint32_t arow256[2]; int ar7[2];
#pragma unroll
        for (int mt = 0; mt < 2; ++mt) {
            int rr = warp_m * 32 + mt * 16 + a_rl;
            arow256[mt] = (uint32_t)rr * 256; ar7[mt] = rr & 7;
        }
        uint32_t brow256[4]; int br7[4];
#pragma unroll
        for (int pj = 0; pj < 4; ++pj) {
            int rr = warp_n * 64 + pj * 16 + b_rl;
            brow256[pj] = (uint32_t)rr * 256; br7[pj] = rr & 7;
        }
        const int gr = lid >> 2;
        const int gc = (lid & 3) << 1;
        float2 pbr[8];
#pragma unroll
        for (int nt = 0; nt < 8; ++nt)
            pbr[nt] = *(const float2*)(postBias + warp_n * 64 + nt * 8 + gc);

        int i = 0;
        for (int tile = blockIdx.x; tile < NT; tile += grid, ++i) {
            int b = i & 1;
            BAR_SYNC(1 + b);
            uint32_t Abase = tiles_u32 + b * 65536;

            float c[2][8][4];
#pragma unroll
            for (int mt = 0; mt < 2; ++mt)
#pragma unroll
                for (int nt = 0; nt < 8; ++nt)
#pragma unroll
                    for (int k = 0; k < 4; ++k) c[mt][nt][k] = 0.f;

#pragma unroll
            for (int ks = 0; ks < 8; ++ks) {
                const int kb = ks * 2;
                uint32_t ahi[2][4], alo[2][4];
#pragma unroll
                for (int mt = 0; mt < 2; ++mt) {
                    uint32_t sw = (uint32_t)(((kb + akq) ^ ar7[mt]) << 4);
                    ldmx4(ahi[mt], Abase + arow256[mt] + sw);
                    ldmx4(alo[mt], Abase + 32768 + arow256[mt] + sw);
                }
#pragma unroll
                for (int pj = 0; pj < 4; ++pj) {
                    uint32_t bh[4], bl[4];
                    uint32_t swb = (uint32_t)(((kb + bkq) ^ br7[pj]) << 4);
                    ldmx4(bh, tiles_u32 + 131072 + brow256[pj] + swb);
                    ldmx4(bl, tiles_u32 + 163840 + brow256[pj] + swb);
#pragma unroll
                    for (int mt = 0; mt < 2; ++mt)
#pragma unroll
                        for (int sub = 0; sub < 2; ++sub) {
                            float* cc = c[mt][pj * 2 + sub];
                            mma16816(cc, ahi[mt], bh + sub * 2);
                            mma16816(cc, ahi[mt], bl + sub * 2);
                            mma16816(cc, alo[mt], bh + sub * 2);
                        }
                }
            }
            BAR_ARRIVE(3 + b);

#pragma unroll
            for (int mt = 0; mt < 2; ++mt) {
                int mrow = tile * 128 + warp_m * 32 + mt * 16 + gr;
                int d0 = dstIdx[mrow];
                int d1 = dstIdx[mrow + 8];
#pragma unroll
                for (int nt = 0; nt < 8; ++nt) {
                    int n = warp_n * 64 + nt * 8 + gc;
                    float o0 = fmaxf(c[mt][nt][0] + pbr[nt].x, 0.f);
                    float o1 = fmaxf(c[mt][nt][1] + pbr[nt].y, 0.f);
                    float o2 = fmaxf(c[mt][nt][2] + pbr[nt].x, 0.f);
                    float o3 = fmaxf(c[mt][nt][3] + pbr[nt].y, 0.f);
                    if (o0 != 0.f || o1 != 0.f) red_add_v2(C + (size_t)d0 * 128 + n, o0, o1);
                    if (o2 != 0.f || o3 != 0.f) red_add_v2(C + (size_t)d1 * 128 + n, o2, o3);
                }
            }
        }
    }
}

// ---------------- fused U1+U2 ----------------
template<int NORM>
__global__ __launch_bounds__(512, 1)
void tc_u1u2(const float* __restrict__ A0, const float* __restrict__ A1,
             const char* __restrict__ Wt1, const float* __restrict__ BU1,
             const char* __restrict__ Wt2, const float* __restrict__ BU2,
             float* __restrict__ C2, const float* __restrict__ accPrev,
             float* __restrict__ accCur, float* __restrict__ aggNext) {
    extern __shared__ char dyn[];
    __shared__ float s_stats[256];
    const int tid = threadIdx.x;
    const int wid = tid >> 5;
    const int lid = tid & 31;
    const int m0  = blockIdx.x * 128;
    uint32_t dyn_u32 = smem_u32(dyn);
    uint32_t pad = ((dyn_u32 + 1023u) & ~1023u) - dyn_u32;
    char* tiles = dyn + pad;
    uint32_t tiles_u32 = dyn_u32 + pad;

    const int warp_m = wid & 3;
    const int warp_n = wid >> 2;
    const int quad = lid >> 3;
    const int lrow = lid & 7;
    const int a_rl = (quad & 1) * 8 + lrow;
    const int akq  = quad >> 1;
    const int b_rl = (quad >> 1) * 8 + lrow;
    const int bkq  = quad & 1;
    uint32_t arow256[2]; int ar7[2];
#pragma unroll
    for (int mt = 0; mt < 2; ++mt) {
        int rr = warp_m * 32 + mt * 16 + a_rl;
        arow256[mt] = (uint32_t)rr * 256; ar7[mt] = rr & 7;
    }
    uint32_t brow256[2]; int br7[2];
#pragma unroll
    for (int pj = 0; pj < 2; ++pj) {
        int rr = warp_n * 32 + pj * 16 + b_rl;
        brow256[pj] = (uint32_t)rr * 256; br7[pj] = rr & 7;
    }
    const int gr = lid >> 2;
    const int gc = (lid & 3) << 1;

    if (NORM) {
        compute_stats(accPrev, m0 >> 10, s_stats, tid);
        __syncthreads();
    }

    // ======== U1 ========
    float c[2][4][4];
#pragma unroll
    for (int mt = 0; mt < 2; ++mt)
#pragma unroll
        for (int nt = 0; nt < 4; ++nt)
#pragma unroll
            for (int i = 0; i < 4; ++i) c[mt][nt][i] = 0.f;

    for (int p = 0; p < 2; ++p) {
        if (p) __syncthreads();
        if (p == 0)
            stage_rows<512, 128, NORM>(A0, m0, tiles, tiles + 32768, s_stats, tid);
        else {
            stage_rows<512, 128, 0>(A1, m0, tiles, tiles + 32768, nullptr, tid);
            const int sr = tid >> 3, ch8 = tid & 7;
#pragma unroll
            for (int pass = 0; pass < 2; ++pass) {
                int node = m0 + sr + pass * 64;
                float4* zr = (float4*)(aggNext + (size_t)node * 128) + ch8;
#pragma unroll
                for (int j = 0; j < 4; ++j)
                    zr[j * 8] = make_float4(0.f, 0.f, 0.f, 0.f);
            }
        }
        {
            const float4* wsrc = (const float4*)(Wt1 + (size_t)p * 65536);
            float4* wdst = (float4*)(tiles + 65536);
#pragma unroll
            for (int j = 0; j < 8; ++j)
                wdst[tid + j * 512] = wsrc[tid + j * 512];
        }
        __syncthreads();

#pragma unroll
        for (int ks = 0; ks < 8; ++ks) {
            const int kb = ks * 2;
            uint32_t ahi[2][4], alo[2][4], bhi[2][4], blo[2][4];
#pragma unroll
            for (int mt = 0; mt < 2; ++mt) {
                uint32_t sw = (uint32_t)(((kb + akq) ^ ar7[mt]) << 4);
                ldmx4(ahi[mt], tiles_u32 + arow256[mt] + sw);
                ldmx4(alo[mt], tiles_u32 + 32768 + arow256[mt] + sw);
            }
#pragma unroll
            for (int pj = 0; pj < 2; ++pj) {
                uint32_t swb = (uint32_t)(((kb + bkq) ^ br7[pj]) << 4);
                ldmx4(bhi[pj], tiles_u32 + 65536 + brow256[pj] + swb);
                ldmx4(blo[pj], tiles_u32 + 98304 + brow256[pj] + swb);
            }
#pragma unroll
            for (int mt = 0; mt < 2; ++mt)
#pragma unroll
                for (int nt = 0; nt < 4; ++nt) {
                    const uint32_t* bh = &bhi[nt >> 1][(nt & 1) * 2];
                    const uint32_t* bl = &blo[nt >> 1][(nt & 1) * 2];
                    mma16816(c[mt][nt], ahi[mt], bh);
                    mma16816(c[mt][nt], ahi[mt], bl);
                    mma16816(c[mt][nt], alo[mt], bh);
                }
        }
    }

    // ======== U1 epilogue -> smem bf16 t1 tile ========
    __syncthreads();
#pragma unroll
    for (int mt = 0; mt < 2; ++mt) {
        const int r1 = warp_m * 32 + mt * 16 + gr;
        const int r2 = r1 + 8;
#pragma unroll
        for (int nt = 0; nt < 4; ++nt) {
            const int n = warp_n * 32 + nt * 8 + gc;
            float2 pb = *(const float2*)(BU1 + n);
            float o0 = fmaxf(c[mt][nt][0] + pb.x, 0.f);
            float o1 = fmaxf(c[mt][nt][1] + pb.y, 0.f);
            float o2 = fmaxf(c[mt][nt][2] + pb.x, 0.f);
            float o3 = fmaxf(c[mt][nt][3] + pb.y, 0.f);
            uint32_t hv, lv;
            split2(o0, o1, hv, lv);
            uint32_t off1 = (uint32_t)(r1 * 256 + ((((n >> 3) ^ (r1 & 7)) << 4) | ((n & 7) << 1)));
            *(uint32_t*)(tiles + off1) = hv;
            *(uint32_t*)(tiles + 32768 + off1) = lv;
            split2(o2, o3, hv, lv);
            uint32_t off2 = (uint32_t)(r2 * 256 + ((((n >> 3) ^ (r2 & 7)) << 4) | ((n & 7) << 1)));
            *(uint32_t*)(tiles + off2) = hv;
            *(uint32_t*)(tiles + 32768 + off2) = lv;
        }
    }
    {
        const float4* wsrc = (const float4*)Wt2;
        float4* wdst = (float4*)(tiles + 65536);
#pragma unroll
        for (int j = 0; j < 8; ++j)
            wdst[tid + j * 512] = wsrc[tid + j * 512];
    }
    __syncthreads();

    // ======== U2 ========
    float c2[2][4][4];
#pragma unroll
    for (int mt = 0; mt < 2; ++mt)
#pragma unroll
        for (int nt = 0; nt < 4; ++nt)
#pragma unroll
            for (int i = 0; i < 4; ++i) c2[mt][nt][i] = 0.f;

#pragma unroll
    for (int ks = 0; ks < 8; ++ks) {
        const int kb = ks * 2;
        uint32_t ahi[2][4], alo[2][4], bhi[2][4], blo[2][4];
#pragma unroll
        for (int mt = 0; mt < 2; ++mt) {
            uint32_t sw = (uint32_t)(((kb + akq) ^ ar7[mt]) << 4);
            ldmx4(ahi[mt], tiles_u32 + arow256[mt] + sw);
            ldmx4(alo[mt], tiles_u32 + 32768 + arow256[mt] + sw);
        }
#pragma unroll
        for (int pj = 0; pj < 2; ++pj) {
            uint32_t swb = (uint32_t)(((kb + bkq) ^ br7[pj]) << 4);
            ldmx4(bhi[pj], tiles_u32 + 65536 + brow256[pj] + swb);
            ldmx4(blo[pj], tiles_u32 + 98304 + brow256[pj] + swb);
        }
#pragma unroll
        for (int mt = 0; mt < 2; ++mt)
#pragma unroll
            for (int nt = 0; nt < 4; ++nt) {
                const uint32_t* bh = &bhi[nt >> 1][(nt & 1) * 2];
                const uint32_t* bl = &blo[nt >> 1][(nt & 1) * 2];
                mma16816(c2[mt][nt], ahi[mt], bh);
                mma16816(c2[mt][nt], ahi[mt], bl);
                mma16816(c2[mt][nt], alo[mt], bh);
            }
    }

    // ======== U2 epilogue ========
    const int batch = m0 >> 10;
    float* accS = accCur + batch * 128;
    float* accQ = accCur + NBATCH * NHID + batch * 128;
#pragma unroll
    for (int nt = 0; nt < 4; ++nt) {
        const int n = warp_n * 32 + nt * 8 + gc;
        float2 pb = *(const float2*)(BU2 + n);
        float s0 = 0.f, s1 = 0.f, q0 = 0.f, q1 = 0.f;
#pragma unroll
        for (int mt = 0; mt < 2; ++mt) {
            int mrow = m0 + warp_m * 32 + mt * 16 + gr;
            float o0 = fmaxf(c2[mt][nt][0] + pb.x, 0.f);
            float o1 = fmaxf(c2[mt][nt][1] + pb.y, 0.f);
            float o2 = fmaxf(c2[mt][nt][2] + pb.x, 0.f);
            float o3 = fmaxf(c2[mt][nt][3] + pb.y, 0.f);
            *(float2*)(C2 + (size_t)mrow * 128 + n)       = make_float2(o0, o1);
            *(float2*)(C2 + (size_t)(mrow + 8) * 128 + n) = make_float2(o2, o3);
            s0 += o0 + o2;
            s1 += o1 + o3;
            q0 += o0 * o0 + o2 * o2;
            q1 += o1 * o1 + o3 * o3;
        }
#pragma unroll
        for (int off = 4; off < 32; off <<= 1) {
            s0 += __shfl_xor_sync(0xFFFFFFFFu, s0, off);
            s1 += __shfl_xor_sync(0xFFFFFFFFu, s1, off);
            q0 += __shfl_xor_sync(0xFFFFFFFFu, q0, off);
            q1 += __shfl_xor_sync(0xFFFFFFFFu, q1, off);
        }
        if (lid < 4) {
            red_add_v2(accS + n, s0, s1);
            red_add_v2(accQ + n, q0, q1);
        }
    }
}

// ---------------- decoder / discrepancy / final ----------------
__global__ void decoder_kernel(const float* __restrict__ H,
                               const float* __restrict__ acc,
                               const float* __restrict__ W,
                               const float* __restrict__ B,
                               float* __restrict__ GX,
                               float* __restrict__ x_out) {
    int gthread = blockIdx.x * blockDim.x + threadIdx.x;
    int n = gthread >> 5;
    int lane = threadIdx.x & 31;
    if (n >= N_NODES) return;
    const float* hr = H + (size_t)n * 128;
    const float* accS = acc + (n >> 10) * 128;
    const float* accQ = accS + NBATCH * NHID;
    float a0 = 0.f, a1 = 0.f, a2 = 0.f, a3 = 0.f;
#pragma unroll
    for (int k = 0; k < 128; k += 32) {
        float s = accS[k + lane];
        float q = accQ[k + lane];
        float mean = s * (1.0f / NSAMPLES);
        float var = q * (1.0f / NSAMPLES) - mean * mean;
        float hv = (hr[k + lane] - mean) * rsqrtf(var + EPSV);
        float4 w = ((const float4*)W)[k + lane];
        a0 += hv * w.x;
        a1 += hv * w.y;
        a2 += hv * w.z;
        a3 += hv * w.w;
    }
#pragma unroll
    for (int off = 16; off > 0; off >>= 1) {
        a0 += __shfl_xor_sync(0xFFFFFFFFu, a0, off);
        a1 += __shfl_xor_sync(0xFFFFFFFFu, a1, off);
        a2 += __shfl_xor_sync(0xFFFFFFFFu, a2, off);
        a3 += __shfl_xor_sync(0xFFFFFFFFu, a3, off);
    }
    if (lane == 0) {
        float z0 = 1.f / (1.f + expf(-(a0 + B[0])));
        float z1 = 1.f / (1.f + expf(-(a1 + B[1])));
        float z2 = 1.f / (1.f + expf(-(a2 + B[2])));
        float z3 = 1.f / (1.f + expf(-(a3 + B[3])));
        ((float4*)GX)[n] = make_float4(z0, z1, z2, z3);
        if (x_out) {
            x_out[n * 4 + 0] = z0;
            x_out[n * 4 + 1] = z1;
            x_out[n * 4 + 2] = z2;
            x_out[n * 4 + 3] = z3;
        }
    }
}

__global__ void disc_kernel(const float* __restrict__ GX) {
    __shared__ float4 sx[NSAMPLES];
    __shared__ float red1[128];
    __shared__ float red2[128];
    int b = blockIdx.x;
    int chunk = blockIdx.y;
    int tid = threadIdx.x;
    const float4* xb = (const float4*)GX + (size_t)b * NSAMPLES;
    for (int i = tid; i < NSAMPLES; i += 128) sx[i] = xb[i];
    __syncthreads();
    int i = chunk * 128 + tid;
    float4 xi = sx[i];
    float p1 = (1.f - xi.x * xi.x) * (1.f - xi.y * xi.y) *
               (1.f - xi.z * xi.z) * (1.f - xi.w * xi.w);
    float s2a = 0.f, s2b = 0.f, s2c = 0.f, s2d = 0.f;
#pragma unroll 2
    for (int j = 0; j < NSAMPLES; j += 4) {
        float4 x0 = sx[j];
        float4 x1 = sx[j + 1];
        float4 x2 = sx[j + 2];
        float4 x3 = sx[j + 3];
        s2a += (1.f - fmaxf(xi.x, x0.x)) * (1.f - fmaxf(xi.y, x0.y)) *
               (1.f - fmaxf(xi.z, x0.z)) * (1.f - fmaxf(xi.w, x0.w));
        s2b += (1.f - fmaxf(xi.x, x1.x)) * (1.f - fmaxf(xi.y, x1.y)) *
               (1.f - fmaxf(xi.z, x1.z)) * (1.f - fmaxf(xi.w, x1.w));
        s2c += (1.f - fmaxf(xi.x, x2.x)) * (1.f - fmaxf(xi.y, x2.y)) *
               (1.f - fmaxf(xi.z, x2.z)) * (1.f - fmaxf(xi.w, x2.w));
        s2d += (1.f - fmaxf(xi.x, x3.x)) * (1.f - fmaxf(xi.y, x3.y)) *
               (1.f - fmaxf(xi.z, x3.z)) * (1.f - fmaxf(xi.w, x3.w));
    }
    float s2 = (s2a + s2b) + (s2c + s2d);
    red1[tid] = p1;
    red2[tid] = s2;
    __syncthreads();
    for (int s = 64; s > 0; s >>= 1) {
        if (tid < s) {
            red1[tid] += red1[tid + s];
            red2[tid] += red2[tid + s];
        }
        __syncthreads();
    }
    if (tid == 0) {
        atomicAdd(&g_dsum[b], red1[0]);
        atomicAdd(&g_dsum[16 + b], red2[0]);
    }
}

__global__ void final_kernel(float* __restrict__ loss_out) {
    if (threadIdx.x == 0 && blockIdx.x == 0) {
        float acc = 0.f;
        const float invN = 1.0f / (float)NSAMPLES;
        for (int b = 0; b < NBATCH; ++b) {
            float s1 = g_dsum[b];
            float s2 = g_dsum[16 + b];
            float v = (1.0f / 81.0f) - invN * 0.125f * s1 + s2 * invN * invN;
            acc += sqrtf(v);
        }
        float loss = acc / (float)NBATCH;
        if (loss_out) *loss_out = loss;
    }
}

// ---------------- launch ----------------
extern "C" void kernel_launch(void* const* d_in, const int* in_sizes, int n_in,
                              void* d_out, int out_size) {
    const float *X, *enc_w, *enc_b, *dec_w, *dec_b;
    const float *m1w, *m1b, *m2w, *m2b, *u1w, *u1b, *u2w, *u2b;
    const int* ei = (const int*)d_in[1];
    X = (const float*)d_in[0];
    bool dictOrder = (in_sizes[5] == 512);
    if (dictOrder) {
        enc_w = (const float*)d_in[3];  enc_b = (const float*)d_in[4];
        dec_w = (const float*)d_in[5];  dec_b = (const float*)d_in[6];
        m1w = (const float*)d_in[7];    m1b = (const float*)d_in[8];
        m2w = (const float*)d_in[9];    m2b = (const float*)d_in[10];
        u1w = (const float*)d_in[11];   u1b = (const float*)d_in[12];
        u2w = (const float*)d_in[13];   u2b = (const float*)d_in[14];
    } else {
        enc_w = (const float*)d_in[3];  enc_b = (const float*)d_in[4];
        m1w = (const float*)d_in[5];    m1b = (const float*)d_in[6];
        m2w = (const float*)d_in[7];    m2b = (const float*)d_in[8];
        u1w = (const float*)d_in[9];    u1b = (const float*)d_in[10];
        u2w = (const float*)d_in[11];   u2b = (const float*)d_in[12];
        dec_w = (const float*)d_in[13]; dec_b = (const float*)d_in[14];
    }
    const int* src = ei;
    const int* dst = ei + N_EDGES;

    void* p;
    float *h_, *Pd, *Ps, *aggA, *aggB, *t2, *gx, *naccA, *naccB;
    char* wt;
    cudaGetSymbolAddress(&p, g_h);      h_   = (float*)p;
    cudaGetSymbolAddress(&p, g_Pd);     Pd   = (float*)p;
    cudaGetSymbolAddress(&p, g_Ps);     Ps   = (float*)p;
    cudaGetSymbolAddress(&p, g_agg);    aggA = (float*)p;
    cudaGetSymbolAddress(&p, g_agg2);   aggB = (float*)p;
    cudaGetSymbolAddress(&p, g_t2);     t2   = (float*)p;
    cudaGetSymbolAddress(&p, g_x);      gx   = (float*)p;
    cudaGetSymbolAddress(&p, g_naccA);  naccA = (float*)p;
    cudaGetSymbolAddress(&p, g_naccB);  naccB = (float*)p;
    cudaGetSymbolAddress(&p, g_wt);     wt   = (char*)p;
    float* aggs[2]  = {aggA, aggB};
    float* naccs[2] = {naccA, naccB};

    float* out = (float*)d_out;
    float* loss_out;
    float* x_out;
    if (out_size >= N_NODES * DIMX + 1) { loss_out = out; x_out = out + 1; }
    else if (out_size == N_NODES * DIMX) { loss_out = nullptr; x_out = out; }
    else { loss_out = out; x_out = nullptr; }

    cudaFuncSetAttribute(tc_pdps<0>, cudaFuncAttributeMaxDynamicSharedMemorySize, PDPS_SMEM);
    cudaFuncSetAttribute(tc_pdps<1>, cudaFuncAttributeMaxDynamicSharedMemorySize, PDPS_SMEM);
    cudaFuncSetAttribute(tc_edge,    cudaFuncAttributeMaxDynamicSharedMemorySize, EDGE_SMEM);
    cudaFuncSetAttribute(tc_u1u2<0>, cudaFuncAttributeMaxDynamicSharedMemorySize, U1_SMEM);
    cudaFuncSetAttribute(tc_u1u2<1>, cudaFuncAttributeMaxDynamicSharedMemorySize, U1_SMEM);

    // ---- weight prep ----
    PrepJobs jobs;
    for (int l = 0; l < NLAYERS; ++l) {
        char* lb = wt + (size_t)l * WT_LAYER_STRIDE;
        jobs.src[l*5+0] = m1w + (size_t)l * 256 * 128;            jobs.dst[l*5+0] = lb + WT_W1A; jobs.nelem[l*5+0] = 128*128;
        jobs.src[l*5+1] = m1w + (size_t)l * 256 * 128 + 128*128;  jobs.dst[l*5+1] = lb + WT_W1B; jobs.nelem[l*5+1] = 128*128;
        jobs.src[l*5+2] = m2w + (size_t)l * 128 * 128;            jobs.dst[l*5+2] = lb + WT_W2;  jobs.nelem[l*5+2] = 128*128;
        jobs.src[l*5+3] = u1w + (size_t)l * 256 * 128;            jobs.dst[l*5+3] = lb + WT_U1;  jobs.nelem[l*5+3] = 256*128;
        jobs.src[l*5+4] = u2w + (size_t)l * 128 * 128;            jobs.dst[l*5+4] = lb + WT_U2;  jobs.nelem[l*5+4] = 128*128;
    }
    prep_w_all<<<dim3(128, 15), 256>>>(jobs);

    encoder_kernel<<<(N_NODES * NHID) / 256, 256>>>(X, enc_w, enc_b, h_);

    for (int l = 0; l < NLAYERS; ++l) {
        char* lb = wt + (size_t)l * WT_LAYER_STRIDE;
        const float* B1  = m1b + l * 128;
        const float* B2  = m2b + l * 128;
        const float* BU1 = u1b + l * 128;
        const float* BU2 = u2b + l * 128;
        const float* Aprev = (l == 0) ? h_ : t2;
        float* aggCur  = aggs[l & 1];
        float* aggNext = aggs[(l + 1) & 1];
        float* accPrev = (l == 0) ? nullptr : naccs[(l - 1) & 1];
        float* accCur  = naccs[l & 1];
        float* zeroAcc = (l == 2) ? accCur : nullptr;

        if (l == 0)
            tc_pdps<0><<<128, 512, PDPS_SMEM>>>(Aprev, lb + WT_W1A, Pd, Ps, nullptr);
        else
            tc_pdps<1><<<128, 512, PDPS_SMEM>>>(Aprev, lb + WT_W1A, Pd, Ps, accPrev);

        tc_edge<<<148, 512, EDGE_SMEM>>>(Pd, Ps, lb + WT_W2, B1, B2, aggCur, dst, src, zeroAcc);

        if (l == 0)
            tc_u1u2<0><<<128, 512, U1_SMEM>>>(Aprev, aggCur, lb + WT_U1, BU1,
                                              lb + WT_U2, BU2, t2, nullptr, accCur, aggNext);
        else
            tc_u1u2<1><<<128, 512, U1_SMEM>>>(Aprev, aggCur, lb + WT_U1, BU1,
                                              lb + WT_U2, BU2, t2, accPrev, accCur, aggNext);
    }

    decoder_kernel<<<(N_NODES * 32) / 256, 256>>>(t2, naccs[(NLAYERS - 1) & 1],
                                                  dec_w, dec_b, gx, x_out);
    disc_kernel<<<dim3(NBATCH, 8), 128>>>(gx);
    final_kernel<<<1, 1>>>(loss_out);
}

// round 16
// speedup vs baseline: 1.0875x; 1.0130x over previous
#include <cuda_runtime.h>
#include <cuda_bf16.h>
#include <math.h>
#include <stdint.h>

// ---------------- problem constants ----------------
#define N_NODES   16384
#define N_EDGES   262144
#define NHID      128
#define NLAYERS   3
#define NBATCH    16
#define NSAMPLES  1024
#define DIMX      4
#define EPSV      1e-5f

#define WT_LAYER_STRIDE 393216
#define WT_W1A 0
#define WT_W1B 65536
#define WT_W2  131072
#define WT_U1  196608
#define WT_U2  327680

#define PDPS_SMEM  197632   // 1K pad + A 64K + W1a/W1b hi/lo 128K
#define EDGE_SMEM  197632   // 1K pad + 2 A bufs (2*64K) + W 64K
#define U1_SMEM    132096   // 1K pad + A 64K + W 64K

#define NPREPJOBS  15
#define PREP_SLOT  32768    // padded per-job element slot in merged encoder

// ---------------- device scratch ----------------
__device__ float g_h [N_NODES * NHID];
__device__ float g_Pd[N_NODES * NHID];
__device__ float g_Ps[N_NODES * NHID];
__device__ float g_agg [N_NODES * NHID];
__device__ float g_agg2[N_NODES * NHID];
__device__ float g_t2[N_NODES * NHID];
__device__ float g_x [N_NODES * DIMX];
__device__ float g_naccA[2 * NBATCH * NHID];
__device__ float g_naccB[2 * NBATCH * NHID];
__device__ float g_dsum[32];
__device__ int   g_done = 0;
__device__ char  g_wt[NLAYERS * WT_LAYER_STRIDE];

// ---------------- helpers ----------------
__device__ __forceinline__ uint32_t smem_u32(const void* p) {
    uint32_t a;
    asm("{ .reg .u64 t; cvta.to.shared.u64 t, %1; cvt.u32.u64 %0, t; }" : "=r"(a) : "l"(p));
    return a;
}
__device__ __forceinline__ void red_add_v2(float* p, float a, float b) {
    asm volatile("red.global.add.v2.f32 [%0], {%1,%2};"
                 :: "l"(p), "f"(a), "f"(b) : "memory");
}
// packed cvt: returns {low = bf16(lo_), high = bf16(hi_)}
__device__ __forceinline__ uint32_t cvt2bf(float hi_, float lo_) {
    uint32_t r;
    asm("cvt.rn.bf16x2.f32 %0, %1, %2;" : "=r"(r) : "f"(hi_), "f"(lo_));
    return r;
}
__device__ __forceinline__ void ldmx4(uint32_t* r, uint32_t addr) {
    asm volatile("ldmatrix.sync.aligned.m8n8.x4.shared.b16 {%0,%1,%2,%3}, [%4];"
                 : "=r"(r[0]), "=r"(r[1]), "=r"(r[2]), "=r"(r[3]) : "r"(addr));
}
__device__ __forceinline__ void mma16816(float* c, const uint32_t* a, const uint32_t* b) {
    asm volatile("mma.sync.aligned.m16n8k16.row.col.f32.bf16.bf16.f32 "
                 "{%0,%1,%2,%3}, {%4,%5,%6,%7}, {%8,%9}, {%0,%1,%2,%3};"
                 : "+f"(c[0]), "+f"(c[1]), "+f"(c[2]), "+f"(c[3])
                 : "r"(a[0]), "r"(a[1]), "r"(a[2]), "r"(a[3]), "r"(b[0]), "r"(b[1]));
}
#define BAR_SYNC(id)   asm volatile("bar.sync %0, 512;"   :: "r"(id) : "memory")
#define BAR_ARRIVE(id) asm volatile("bar.arrive %0, 512;" :: "r"(id) : "memory")

// split float pair into bf16 hi/lo packed words (rounding identical to __float2bfloat16 path)
__device__ __forceinline__ void split2(float a, float b, uint32_t& hv, uint32_t& lv) {
    hv = cvt2bf(b, a);
    float fa = __uint_as_float(hv << 16);
    float fb = __uint_as_float(hv & 0xFFFF0000u);
    lv = cvt2bf(b - fb, a - fa);
}
__device__ __forceinline__ void split4(float4 v, uint2& hv, uint2& lv) {
    split2(v.x, v.y, hv.x, lv.x);
    split2(v.z, v.w, hv.y, lv.y);
}

__device__ __forceinline__ void compute_stats(const float* __restrict__ acc,
                                              int batch, float* s_stats, int tid) {
    if (tid < 128) {
        float s = acc[batch * 128 + tid];
        float q = acc[NBATCH * NHID + batch * 128 + tid];
        float mean = s * (1.0f / NSAMPLES);
        float var = q * (1.0f / NSAMPLES) - mean * mean;
        s_stats[tid] = mean;
        s_stats[128 + tid] = rsqrtf(var + EPSV);
    }
}

// ---------------- weight prep jobs ----------------
struct PrepJobs {
    const float* src[NPREPJOBS];
    char* dst[NPREPJOBS];
    int nelem[NPREPJOBS];
};

// ---------------- encoder (+ fused weight prep + buffer zeroing) ----------------
__global__ void encoder_kernel(const float* __restrict__ X,
                               const float* __restrict__ W,
                               const float* __restrict__ B,
                               float* __restrict__ H,
                               PrepJobs jobs) {
    int idx = blockIdx.x * blockDim.x + threadIdx.x;
    int n = idx >> 7;
    int c = idx & 127;
    float4 xv = ((const float4*)X)[n];
    float v = B[c];
    v += xv.x * W[c];
    v += xv.y * W[128 + c];
    v += xv.z * W[256 + c];
    v += xv.w * W[384 + c];
    H[idx] = v;
    g_agg[idx] = 0.f;
    if (idx < 2 * NBATCH * NHID) { g_naccA[idx] = 0.f; g_naccB[idx] = 0.f; }
    if (idx < 32) g_dsum[idx] = 0.f;

    // fused weight prep: flat job mapping (job slot = 32768 elements)
    if (idx < NPREPJOBS * PREP_SLOT) {
        int m = idx / PREP_SLOT;
        int e = idx - m * PREP_SLOT;
        if (e < jobs.nelem[m]) {
            const float* Ws = jobs.src[m];
            char* out = jobs.dst[m];
            int k = e >> 7, nn = e & 127;
            float w = Ws[e];
            __nv_bfloat16 hi = __float2bfloat16(w);
            __nv_bfloat16 lo = __float2bfloat16(w - __bfloat162float(hi));
            int phase = k >> 7, kk = k & 127;
            uint32_t off = (uint32_t)(nn * 256 + ((((kk >> 3) ^ (nn & 7)) << 4) | ((kk & 7) << 1)));
            *(__nv_bfloat16*)(out + (size_t)phase * 65536 + off) = hi;
            *(__nv_bfloat16*)(out + (size_t)phase * 65536 + 32768 + off) = lo;
        }
    }
}

// ---------------- coalesced staging ----------------
template<int NTHREADS, int NROWS, int NORM>
__device__ __forceinline__ void stage_rows(
    const float* __restrict__ Abase, int row0,
    char* __restrict__ Ahi, char* __restrict__ Alo,
    const float* __restrict__ stats, int tid)
{
    const int sr  = tid >> 3;
    const int ch8 = tid & 7;
    const int ROWS_PER_PASS = NTHREADS / 8;
    const int NPASS = NROWS / ROWS_PER_PASS;
#pragma unroll
    for (int pass = 0; pass < NPASS; ++pass) {
        const int r = sr + pass * ROWS_PER_PASS;
        const int node = row0 + r;
        const float* arow = Abase + (size_t)node * 128;
        const int r7 = r & 7;
        const uint32_t r256 = (uint32_t)r * 256;
#pragma unroll
        for (int j = 0; j < 4; ++j) {
            const int c4 = (ch8 + j * 8) * 4;
            float4 v = *(const float4*)(arow + c4);
            if (NORM) {
                float4 m  = *(const float4*)(stats + c4);
                float4 iv = *(const float4*)(stats + 128 + c4);
                v.x = (v.x - m.x) * iv.x;
                v.y = (v.y - m.y) * iv.y;
                v.z = (v.z - m.z) * iv.z;
                v.w = (v.w - m.w) * iv.w;
            }
            uint2 hv, lv;
            split4(v, hv, lv);
            uint32_t off = r256 + ((((c4 >> 3) ^ r7) << 4) | ((c4 & 7) << 1));
            *(uint2*)(Ahi + off) = hv;
            *(uint2*)(Alo + off) = lv;
        }
    }
}

// ---------------- PdPs ----------------
template<int NORM>
__global__ __launch_bounds__(512, 1)
void tc_pdps(const float* __restrict__ A0, const char* __restrict__ Wt,
             float* __restrict__ Pd, float* __restrict__ Ps,
             const float* __restrict__ accPrev) {
    extern __shared__ char dyn[];
    __shared__ float s_stats[256];
    const int tid = threadIdx.x;
    const int wid = tid >> 5;
    const int lid = tid & 31;
    const int m0  = blockIdx.x * 128;
    uint32_t dyn_u32 = smem_u32(dyn);
    uint32_t pad = ((dyn_u32 + 1023u) & ~1023u) - dyn_u32;
    char* tiles = dyn + pad;
    uint32_t tiles_u32 = dyn_u32 + pad;

    if (NORM) {
        compute_stats(accPrev, m0 >> 10, s_stats, tid);
        __syncthreads();
    }
    stage_rows<512, 128, NORM>(A0, m0, tiles, tiles + 32768, s_stats, tid);
    {
        const float4* wsrc = (const float4*)Wt;
        float4* wdst = (float4*)(tiles + 65536);
#pragma unroll
        for (int j = 0; j < 16; ++j)
            wdst[tid + j * 512] = wsrc[tid + j * 512];
    }
    __syncthreads();

    const int warp_m = wid & 3;
    const int warp_n = wid >> 2;
    const int quad = lid >> 3;
    const int lrow = lid & 7;
    const int a_rl = (quad & 1) * 8 + lrow;
    const int akq  = quad >> 1;
    const int b_rl = (quad >> 1) * 8 + lrow;
    const int bkq  = quad & 1;
    uint32_t arow256[2]; int ar7[2];
#pragma unroll
    for (int mt = 0; mt < 2; ++mt) {
        int rr = warp_m * 32 + mt * 16 + a_rl;
        arow256[mt] = (uint32_t)rr * 256; ar7[mt] = rr & 7;
    }
    uint32_t brow256[2]; int br7[2];
#pragma unroll
    for (int pj = 0; pj < 2; ++pj) {
        int rr = warp_n * 32 + pj * 16 + b_rl;
        brow256[pj] = (uint32_t)rr * 256; br7[pj] = rr & 7;
    }
    const int gr = lid >> 2;
    const int gc = (lid & 3) << 1;

#pragma unroll
    for (int h2 = 0; h2 < 2; ++h2) {
        const uint32_t wb = tiles_u32 + 65536 + (uint32_t)h2 * 65536;
        float c[2][4][4];
#pragma unroll
        for (int mt = 0; mt < 2; ++mt)
#pragma unroll
            for (int nt = 0; nt < 4; ++nt)
#pragma unroll
                for (int i = 0; i < 4; ++i) c[mt][nt][i] = 0.f;

#pragma unroll
        for (int ks = 0; ks < 8; ++ks) {
            const int kb = ks * 2;
            uint32_t ahi[2][4], alo[2][4], bhi[2][4], blo[2][4];
#pragma unroll
            for (int mt = 0; mt < 2; ++mt) {
                uint32_t sw = (uint32_t)(((kb + akq) ^ ar7[mt]) << 4);
                ldmx4(ahi[mt], tiles_u32 + arow256[mt] + sw);
                ldmx4(alo[mt], tiles_u32 + 32768 + arow256[mt] + sw);
            }
#pragma unroll
            for (int pj = 0; pj < 2; ++pj) {
                uint32_t swb = (uint32_t)(((kb + bkq) ^ br7[pj]) << 4);
                ldmx4(bhi[pj], wb + brow256[pj] + swb);
                ldmx4(blo[pj], wb + 32768 + brow256[pj] + swb);
            }
#pragma unroll
            for (int mt = 0; mt < 2; ++mt)
#pragma unroll
                for (int nt = 0; nt < 4; ++nt) {
                    const uint32_t* bh = &bhi[nt >> 1][(nt & 1) * 2];
                    const uint32_t* bl = &blo[nt >> 1][(nt & 1) * 2];
                    mma16816(c[mt][nt], ahi[mt], bh);
                    mma16816(c[mt][nt], ahi[mt], bl);
                    mma16816(c[mt][nt], alo[mt], bh);
                }
        }

        float* C = h2 ? Ps : Pd;
#pragma unroll
        for (int mt = 0; mt < 2; ++mt) {
            int mrow = m0 + warp_m * 32 + mt * 16 + gr;
#pragma unroll
            for (int nt = 0; nt < 4; ++nt) {
                int n = warp_n * 32 + nt * 8 + gc;
                *(float2*)(C + (size_t)mrow * 128 + n) =
                    make_float2(c[mt][nt][0], c[mt][nt][1]);
                *(float2*)(C + (size_t)(mrow + 8) * 128 + n) =
                    make_float2(c[mt][nt][2], c[mt][nt][3]);
            }
        }
    }
}

// ---------------- edge GEMM: persistent, warp-specialized ----------------
__global__ __launch_bounds__(512, 1)
void tc_edge(const float* __restrict__ Pd, const float* __restrict__ Ps,
             const char* __restrict__ Wt,
             const float* __restrict__ preBias, const float* __restrict__ postBias,
             float* __restrict__ C,
             const int* __restrict__ dstIdx, const int* __restrict__ srcIdx,
             float* __restrict__ zeroAcc) {
    extern __shared__ char dyn[];
    const int tid = threadIdx.x;
    const int wid = tid >> 5;
    const int lid = tid & 31;
    uint32_t dyn_u32 = smem_u32(dyn);
    uint32_t pad = ((dyn_u32 + 1023u) & ~1023u) - dyn_u32;
    char* tiles = dyn + pad;
    uint32_t tiles_u32 = dyn_u32 + pad;
    // buf0 @0 (hi 32K, lo @32K), buf1 @64K, W @128K (hi, lo @+32K)

    if (zeroAcc && blockIdx.x == 0) {
        ((float4*)zeroAcc)[tid] = make_float4(0.f, 0.f, 0.f, 0.f);
        ((float4*)zeroAcc)[tid + 512] = make_float4(0.f, 0.f, 0.f, 0.f);
    }
    {
        const float4* wsrc = (const float4*)Wt;
        float4* wdst = (float4*)(tiles + 131072);
#pragma unroll
        for (int j = 0; j < 8; ++j)
            wdst[tid + j * 512] = wsrc[tid + j * 512];
    }
    __syncthreads();

    const int grid = gridDim.x;
    const int NT = N_EDGES / 128;

    if (wid >= 8) {
        // ---------------- producer ----------------
        const int pw   = wid - 8;
        const int esub = lid >> 3;
        const int ch8  = lid & 7;
        float4 bias4[4];
#pragma unroll
        for (int cg = 0; cg < 4; ++cg)
            bias4[cg] = *(const float4*)(preBias + (ch8 + cg * 8) * 4);
        int i = 0;
        for (int tile = blockIdx.x; tile < NT; tile += grid, ++i) {
            int b = i & 1;
            int di[4], si[4];
#pragma unroll
            for (int eg = 0; eg < 4; ++eg) {
                const int e = tile * 128 + pw * 16 + eg * 4 + esub;
                di[eg] = dstIdx[e];
                si[eg] = srcIdx[e];
            }
            if (i >= 2) BAR_SYNC(3 + b);
            char* Ah = tiles + b * 65536;
            char* Al = Ah + 32768;
#pragma unroll
            for (int eg = 0; eg < 4; ++eg) {
                const int elocal = pw * 16 + eg * 4 + esub;
                const float* pd = Pd + (size_t)di[eg] * 128;
                const float* ps = Ps + (size_t)si[eg] * 128;
                const int r7 = elocal & 7;
                const uint32_t r256 = (uint32_t)elocal * 256;
#pragma unroll
                for (int cg = 0; cg < 4; ++cg) {
                    const int c4 = (ch8 + cg * 8) * 4;
                    float4 a  = *(const float4*)(pd + c4);
                    float4 s  = *(const float4*)(ps + c4);
                    float4 v;
                    v.x = fmaxf(a.x + s.x + bias4[cg].x, 0.f);
                    v.y = fmaxf(a.y + s.y + bias4[cg].y, 0.f);
                    v.z = fmaxf(a.z + s.z + bias4[cg].z, 0.f);
                    v.w = fmaxf(a.w + s.w + bias4[cg].w, 0.f);
                    uint2 hv, lv;
                    split4(v, hv, lv);
                    uint32_t off = r256 + ((((c4 >> 3) ^ r7) << 4) | ((c4 & 7) << 1));
                    *(uint2*)(Ah + off) = hv;
                    *(uint2*)(Al + off) = lv;
                }
            }
            __threadfence_block();
            BAR_ARRIVE(1 + b);
        }
    } else {
        // ---------------- consumer ----------------
        const int warp_m = wid & 3;
        const int warp_n = wid >> 2;
        const int quad = lid >> 3;
        const int lrow = lid & 7;
        const int a_rl = (quad & 1) * 8 + lrow;
        const int akq  = quad >> 1;
        const int b_rl = (quad >> 1) * 8 + lrow;
        const int bkq  = quad & 1;
        uint32_t arow256[2]; int ar7[2];
#pragma unroll
        for (int mt = 0; mt < 2; ++mt) {
            int rr = warp_m * 32 + mt * 16 + a_rl;
            arow256[mt] = (uint32_t)rr * 256; ar7[mt] = rr & 7;
        }
        uint32_t brow256[4]; int br7[4];
#pragma unroll
        for (int pj = 0; pj < 4; ++pj) {
            int rr = warp_n * 64 + pj * 16 + b_rl;
            brow256[pj] = (uint32_t)rr * 256; br7[pj] = rr & 7;
        }
        const int gr = lid >> 2;
        const int gc = (lid & 3) << 1;
        float2 pbr[8];
#pragma unroll
        for (int nt = 0; nt < 8; ++nt)
            pbr[nt] = *(const float2*)(postBias + warp_n * 64 + nt * 8 + gc);

        int i = 0;
        for (int tile = blockIdx.x; tile < NT; tile += grid, ++i) {
            int b = i & 1;
            BAR_SYNC(1 + b);
            uint32_t Abase = tiles_u32 + b * 65536;

            float c[2][8][4];
#pragma unroll
            for (int mt = 0; mt < 2; ++mt)
#pragma unroll
                for (int nt = 0; nt < 8; ++nt)
#pragma unroll
                    for (int k = 0; k < 4; ++k) c[mt][nt][k] = 0.f;

#pragma unroll
            for (int ks = 0; ks < 8; ++ks) {
                const int kb = ks * 2;
                uint32_t ahi[2][4], alo[2][4];
#pragma unroll
                for (int mt = 0; mt < 2; ++mt) {
                    uint32_t sw = (uint32_t)(((kb + akq) ^ ar7[mt]) << 4);
                    ldmx4(ahi[mt], Abase + arow256[mt] + sw);
                    ldmx4(alo[mt], Abase + 32768 + arow256[mt] + sw);
                }
#pragma unroll
                for (int pj = 0; pj < 4; ++pj) {
                    uint32_t bh[4], bl[4];
                    uint32_t swb = (uint32_t)(((kb + bkq) ^ br7[pj]) << 4);
                    ldmx4(bh, tiles_u32 + 131072 + brow256[pj] + swb);
                    ldmx4(bl, tiles_u32 + 163840 + brow256[pj] + swb);
#pragma unroll
                    for (int mt = 0; mt < 2; ++mt)
#pragma unroll
                        for (int sub = 0; sub < 2; ++sub) {
                            float* cc = c[mt][pj * 2 + sub];
                            mma16816(cc, ahi[mt], bh + sub * 2);
                            mma16816(cc, ahi[mt], bl + sub * 2);
                            mma16816(cc, alo[mt], bh + sub * 2);
                        }
                }
            }
            BAR_ARRIVE(3 + b);

#pragma unroll
            for (int mt = 0; mt < 2; ++mt) {
                int mrow = tile * 128 + warp_m * 32 + mt * 16 + gr;
                int d0 = dstIdx[mrow];
                int d1 = dstIdx[mrow + 8];
#pragma unroll
                for (int nt = 0; nt < 8; ++nt) {
                    int n = warp_n * 64 + nt * 8 + gc;
                    float o0 = fmaxf(c[mt][nt][0] + pbr[nt].x, 0.f);
                    float o1 = fmaxf(c[mt][nt][1] + pbr[nt].y, 0.f);
                    float o2 = fmaxf(c[mt][nt][2] + pbr[nt].x, 0.f);
                    float o3 = fmaxf(c[mt][nt][3] + pbr[nt].y, 0.f);
                    if (o0 != 0.f || o1 != 0.f) red_add_v2(C + (size_t)d0 * 128 + n, o0, o1);
                    if (o2 != 0.f || o3 != 0.f) red_add_v2(C + (size_t)d1 * 128 + n, o2, o3);
                }
            }
        }
    }
}

// ---------------- fused U1+U2 ----------------
template<int NORM>
__global__ __launch_bounds__(512, 1)
void tc_u1u2(const float* __restrict__ A0, const float* __restrict__ A1,
             const char* __restrict__ Wt1, const float* __restrict__ BU1,
             const char* __restrict__ Wt2, const float* __restrict__ BU2,
             float* __restrict__ C2, const float* __restrict__ accPrev,
             float* __restrict__ accCur, float* __restrict__ aggNext) {
    extern __shared__ char dyn[];
    __shared__ float s_stats[256];
    const int tid = threadIdx.x;
    const int wid = tid >> 5;
    const int lid = tid & 31;
    const int m0  = blockIdx.x * 128;
    uint32_t dyn_u32 = smem_u32(dyn);
    uint32_t pad = ((dyn_u32 + 1023u) & ~1023u) - dyn_u32;
    char* tiles = dyn + pad;
    uint32_t tiles_u32 = dyn_u32 + pad;

    const int warp_m = wid & 3;
    const int warp_n = wid >> 2;
    const int quad = lid >> 3;
    const int lrow = lid & 7;
    const int a_rl = (quad & 1) * 8 + lrow;
    const int akq  = quad >> 1;
    const int b_rl = (quad >> 1) * 8 + lrow;
    const int bkq  = quad & 1;
    uint32_t arow256[2]; int ar7[2];
#pragma unroll
    for (int mt = 0; mt < 2; ++mt) {
        int rr = warp_m * 32 + mt * 16 + a_rl;
        arow256[mt] = (uint32_t)rr * 256; ar7[mt] = rr & 7;
    }
    uint32_t brow256[2]; int br7[2];
#pragma unroll
    for (int pj = 0; pj < 2; ++pj) {
        int rr = warp_n * 32 + pj * 16 + b_rl;
        brow256[pj] = (uint32_t)rr * 256; br7[pj] = rr & 7;
    }
    const int gr = lid >> 2;
    const int gc = (lid & 3) << 1;

    if (NORM) {
        compute_stats(accPrev, m0 >> 10, s_stats, tid);
        __syncthreads();
    }

    // ======== U1 ========
    float c[2][4][4];
#pragma unroll
    for (int mt = 0; mt < 2; ++mt)
#pragma unroll
        for (int nt = 0; nt < 4; ++nt)
#pragma unroll
            for (int i = 0; i < 4; ++i) c[mt][nt][i] = 0.f;

    for (int p = 0; p < 2; ++p) {
        if (p) __syncthreads();
        if (p == 0)
            stage_rows<512, 128, NORM>(A0, m0, tiles, tiles + 32768, s_stats, tid);
        else {
            stage_rows<512, 128, 0>(A1, m0, tiles, tiles + 32768, nullptr, tid);
            const int sr = tid >> 3, ch8 = tid & 7;
#pragma unroll
            for (int pass = 0; pass < 2; ++pass) {
                int node = m0 + sr + pass * 64;
                float4* zr = (float4*)(aggNext + (size_t)node * 128) + ch8;
#pragma unroll
                for (int j = 0; j < 4; ++j)
                    zr[j * 8] = make_float4(0.f, 0.f, 0.f, 0.f);
            }
        }
        {
            const float4* wsrc = (const float4*)(Wt1 + (size_t)p * 65536);
            float4* wdst = (float4*)(tiles + 65536);
#pragma unroll
            for (int j = 0; j < 8; ++j)
                wdst[tid + j * 512] = wsrc[tid + j * 512];
        }
        __syncthreads();

#pragma unroll
        for (int ks = 0; ks < 8; ++ks) {
            const int kb = ks * 2;
            uint32_t ahi[2][4], alo[2][4], bhi[2][4], blo[2][4];
#pragma unroll
            for (int mt = 0; mt < 2; ++mt) {
                uint32_t sw = (uint32_t)(((kb + akq) ^ ar7[mt]) << 4);
                ldmx4(ahi[mt], tiles_u32 + arow256[mt] + sw);
                ldmx4(alo[mt], tiles_u32 + 32768 + arow256[mt] + sw);
            }
#pragma unroll
            for (int pj = 0; pj < 2; ++pj) {
                uint32_t swb = (uint32_t)(((kb + bkq) ^ br7[pj]) << 4);
                ldmx4(bhi[pj], tiles_u32 + 65536 + brow256[pj] + swb);
                ldmx4(blo[pj], tiles_u32 + 98304 + brow256[pj] + swb);
            }
#pragma unroll
            for (int mt = 0; mt < 2; ++mt)
#pragma unroll
                for (int nt = 0; nt < 4; ++nt) {
                    const uint32_t* bh = &bhi[nt >> 1][(nt & 1) * 2];
                    const uint32_t* bl = &blo[nt >> 1][(nt & 1) * 2];
                    mma16816(c[mt][nt], ahi[mt], bh);
                    mma16816(c[mt][nt], ahi[mt], bl);
                    mma16816(c[mt][nt], alo[mt], bh);
                }
        }
    }

    // ======== U1 epilogue -> smem bf16 t1 tile ========
    __syncthreads();
#pragma unroll
    for (int mt = 0; mt < 2; ++mt) {
        const int r1 = warp_m * 32 + mt * 16 + gr;
        const int r2 = r1 + 8;
#pragma unroll
        for (int nt = 0; nt < 4; ++nt) {
            const int n = warp_n * 32 + nt * 8 + gc;
            float2 pb = *(const float2*)(BU1 + n);
            float o0 = fmaxf(c[mt][nt][0] + pb.x, 0.f);
            float o1 = fmaxf(c[mt][nt][1] + pb.y, 0.f);
            float o2 = fmaxf(c[mt][nt][2] + pb.x, 0.f);
            float o3 = fmaxf(c[mt][nt][3] + pb.y, 0.f);
            uint32_t hv, lv;
            split2(o0, o1, hv, lv);
            uint32_t off1 = (uint32_t)(r1 * 256 + ((((n >> 3) ^ (r1 & 7)) << 4) | ((n & 7) << 1)));
            *(uint32_t*)(tiles + off1) = hv;
            *(uint32_t*)(tiles + 32768 + off1) = lv;
            split2(o2, o3, hv, lv);
            uint32_t off2 = (uint32_t)(r2 * 256 + ((((n >> 3) ^ (r2 & 7)) << 4) | ((n & 7) << 1)));
            *(uint32_t*)(tiles + off2) = hv;
            *(uint32_t*)(tiles + 32768 + off2) = lv;
        }
    }
    {
        const float4* wsrc = (const float4*)Wt2;
        float4* wdst = (float4*)(tiles + 65536);
#pragma unroll
        for (int j = 0; j < 8; ++j)
            wdst[tid + j * 512] = wsrc[tid + j * 512];
    }
    __syncthreads();

    // ======== U2 ========
    float c2[2][4][4];
#pragma unroll
    for (int mt = 0; mt < 2; ++mt)
#pragma unroll
        for (int nt = 0; nt < 4; ++nt)
#pragma unroll
            for (int i = 0; i < 4; ++i) c2[mt][nt][i] = 0.f;

#pragma unroll
    for (int ks = 0; ks < 8; ++ks) {
        const int kb = ks * 2;
        uint32_t ahi[2][4], alo[2][4], bhi[2][4], blo[2][4];
#pragma unroll
        for (int mt = 0; mt < 2; ++mt) {
            uint32_t sw = (uint32_t)(((kb + akq) ^ ar7[mt]) << 4);
            ldmx4(ahi[mt], tiles_u32 + arow256[mt] + sw);
            ldmx4(alo[mt], tiles_u32 + 32768 + arow256[mt] + sw);
        }
#pragma unroll
        for (int pj = 0; pj < 2; ++pj) {
            uint32_t swb = (uint32_t)(((kb + bkq) ^ br7[pj]) << 4);
            ldmx4(bhi[pj], tiles_u32 + 65536 + brow256[pj] + swb);
            ldmx4(blo[pj], tiles_u32 + 98304 + brow256[pj] + swb);
        }
#pragma unroll
        for (int mt = 0; mt < 2; ++mt)
#pragma unroll
            for (int nt = 0; nt < 4; ++nt) {
                const uint32_t* bh = &bhi[nt >> 1][(nt & 1) * 2];
                const uint32_t* bl = &blo[nt >> 1][(nt & 1) * 2];
                mma16816(c2[mt][nt], ahi[mt], bh);
                mma16816(c2[mt][nt], ahi[mt], bl);
                mma16816(c2[mt][nt], alo[mt], bh);
            }
    }

    // ======== U2 epilogue ========
    const int batch = m0 >> 10;
    float* accS = accCur + batch * 128;
    float* accQ = accCur + NBATCH * NHID + batch * 128;
#pragma unroll
    for (int nt = 0; nt < 4; ++nt) {
        const int n = warp_n * 32 + nt * 8 + gc;
        float2 pb = *(const float2*)(BU2 + n);
        float s0 = 0.f, s1 = 0.f, q0 = 0.f, q1 = 0.f;
#pragma unroll
        for (int mt = 0; mt < 2; ++mt) {
            int mrow = m0 + warp_m * 32 + mt * 16 + gr;
            float o0 = fmaxf(c2[mt][nt][0] + pb.x, 0.f);
            float o1 = fmaxf(c2[mt][nt][1] + pb.y, 0.f);
            float o2 = fmaxf(c2[mt][nt][2] + pb.x, 0.f);
            float o3 = fmaxf(c2[mt][nt][3] + pb.y, 0.f);
            *(float2*)(C2 + (size_t)mrow * 128 + n)       = make_float2(o0, o1);
            *(float2*)(C2 + (size_t)(mrow + 8) * 128 + n) = make_float2(o2, o3);
            s0 += o0 + o2;
            s1 += o1 + o3;
            q0 += o0 * o0 + o2 * o2;
            q1 += o1 * o1 + o3 * o3;
        }
#pragma unroll
        for (int off = 4; off < 32; off <<= 1) {
            s0 += __shfl_xor_sync(0xFFFFFFFFu, s0, off);
            s1 += __shfl_xor_sync(0xFFFFFFFFu, s1, off);
            q0 += __shfl_xor_sync(0xFFFFFFFFu, q0, off);
            q1 += __shfl_xor_sync(0xFFFFFFFFu, q1, off);
        }
        if (lid < 4) {
            red_add_v2(accS + n, s0, s1);
            red_add_v2(accQ + n, q0, q1);
        }
    }
}

// ---------------- decoder ----------------
__global__ void decoder_kernel(const float* __restrict__ H,
                               const float* __restrict__ acc,
                               const float* __restrict__ W,
                               const float* __restrict__ B,
                               float* __restrict__ GX,
                               float* __restrict__ x_out) {
    int gthread = blockIdx.x * blockDim.x + threadIdx.x;
    int n = gthread >> 5;
    int lane = threadIdx.x & 31;
    if (n >= N_NODES) return;
    const float* hr = H + (size_t)n * 128;
    const float* accS = acc + (n >> 10) * 128;
    const float* accQ = accS + NBATCH * NHID;
    float a0 = 0.f, a1 = 0.f, a2 = 0.f, a3 = 0.f;
#pragma unroll
    for (int k = 0; k < 128; k += 32) {
        float s = accS[k + lane];
        float q = accQ[k + lane];
        float mean = s * (1.0f / NSAMPLES);
        float var = q * (1.0f / NSAMPLES) - mean * mean;
        float hv = (hr[k + lane] - mean) * rsqrtf(var + EPSV);
        float4 w = ((const float4*)W)[k + lane];
        a0 += hv * w.x;
        a1 += hv * w.y;
        a2 += hv * w.z;
        a3 += hv * w.w;
    }
#pragma unroll
    for (int off = 16; off > 0; off >>= 1) {
        a0 += __shfl_xor_sync(0xFFFFFFFFu, a0, off);
        a1 += __shfl_xor_sync(0xFFFFFFFFu, a1, off);
        a2 += __shfl_xor_sync(0xFFFFFFFFu, a2, off);
        a3 += __shfl_xor_sync(0xFFFFFFFFu, a3, off);
    }
    if (lane == 0) {
        float z0 = 1.f / (1.f + expf(-(a0 + B[0])));
        float z1 = 1.f / (1.f + expf(-(a1 + B[1])));
        float z2 = 1.f / (1.f + expf(-(a2 + B[2])));
        float z3 = 1.f / (1.f + expf(-(a3 + B[3])));
        ((float4*)GX)[n] = make_float4(z0, z1, z2, z3);
        if (x_out) {
            x_out[n * 4 + 0] = z0;
            x_out[n * 4 + 1] = z1;
            x_out[n * 4 + 2] = z2;
            x_out[n * 4 + 3] = z3;
        }
    }
}

// ---------------- discrepancy (+ fused loss finalize via ticket) ----------------
__global__ void disc_kernel(const float* __restrict__ GX, float* __restrict__ loss_out) {
    __shared__ float4 sx[NSAMPLES];
    __shared__ float red1[128];
    __shared__ float red2[128];
    int b = blockIdx.x;
    int chunk = blockIdx.y;
    int tid = threadIdx.x;
    const float4* xb = (const float4*)GX + (size_t)b * NSAMPLES;
    for (int i = tid; i < NSAMPLES; i += 128) sx[i] = xb[i];
    __syncthreads();
    int i = chunk * 128 + tid;
    float4 xi = sx[i];
    float p1 = (1.f - xi.x * xi.x) * (1.f - xi.y * xi.y) *
               (1.f - xi.z * xi.z) * (1.f - xi.w * xi.w);
    float s2a = 0.f, s2b = 0.f, s2c = 0.f, s2d = 0.f;
#pragma unroll 2
    for (int j = 0; j < NSAMPLES; j += 4) {
        float4 x0 = sx[j];
        float4 x1 = sx[j + 1];
        float4 x2 = sx[j + 2];
        float4 x3 = sx[j + 3];
        s2a += (1.f - fmaxf(xi.x, x0.x)) * (1.f - fmaxf(xi.y, x0.y)) *
               (1.f - fmaxf(xi.z, x0.z)) * (1.f - fmaxf(xi.w, x0.w));
        s2b += (1.f - fmaxf(xi.x, x1.x)) * (1.f - fmaxf(xi.y, x1.y)) *
               (1.f - fmaxf(xi.z, x1.z)) * (1.f - fmaxf(xi.w, x1.w));
        s2c += (1.f - fmaxf(xi.x, x2.x)) * (1.f - fmaxf(xi.y, x2.y)) *
               (1.f - fmaxf(xi.z, x2.z)) * (1.f - fmaxf(xi.w, x2.w));
        s2d += (1.f - fmaxf(xi.x, x3.x)) * (1.f - fmaxf(xi.y, x3.y)) *
               (1.f - fmaxf(xi.z, x3.z)) * (1.f - fmaxf(xi.w, x3.w));
    }
    float s2 = (s2a + s2b) + (s2c + s2d);
    red1[tid] = p1;
    red2[tid] = s2;
    __syncthreads();
    for (int s = 64; s > 0; s >>= 1) {
        if (tid < s) {
            red1[tid] += red1[tid + s];
            red2[tid] += red2[tid + s];
        }
        __syncthreads();
    }
    if (tid == 0) {
        atomicAdd(&g_dsum[b], red1[0]);
        atomicAdd(&g_dsum[16 + b], red2[0]);
        __threadfence();
        int ticket = atomicAdd(&g_done, 1);
        if (ticket == NBATCH * 8 - 1) {   // last of 128 blocks
            g_done = 0;                    // self-reset for next replay
            float acc = 0.f;
            const float invN = 1.0f / (float)NSAMPLES;
            for (int bb = 0; bb < NBATCH; ++bb) {
                float s1v = g_dsum[bb];
                float s2v = g_dsum[16 + bb];
                float v = (1.0f / 81.0f) - invN * 0.125f * s1v + s2v * invN * invN;
                acc += sqrtf(v);
            }
            if (loss_out) *loss_out = acc / (float)NBATCH;
        }
    }
}

// ---------------- launch ----------------
extern "C" void kernel_launch(void* const* d_in, const int* in_sizes, int n_in,
                              void* d_out, int out_size) {
    const float *X, *enc_w, *enc_b, *dec_w, *dec_b;
    const float *m1w, *m1b, *m2w, *m2b, *u1w, *u1b, *u2w, *u2b;
    const int* ei = (const int*)d_in[1];
    X = (const float*)d_in[0];
    bool dictOrder = (in_sizes[5] == 512);
    if (dictOrder) {
        enc_w = (const float*)d_in[3];  enc_b = (const float*)d_in[4];
        dec_w = (const float*)d_in[5];  dec_b = (const float*)d_in[6];
        m1w = (const float*)d_in[7];    m1b = (const float*)d_in[8];
        m2w = (const float*)d_in[9];    m2b = (const float*)d_in[10];
        u1w = (const float*)d_in[11];   u1b = (const float*)d_in[12];
        u2w = (const float*)d_in[13];   u2b = (const float*)d_in[14];
    } else {
        enc_w = (const float*)d_in[3];  enc_b = (const float*)d_in[4];
        m1w = (const float*)d_in[5];    m1b = (const float*)d_in[6];
        m2w = (const float*)d_in[7];    m2b = (const float*)d_in[8];
        u1w = (const float*)d_in[9];    u1b = (const float*)d_in[10];
        u2w = (const float*)d_in[11];   u2b = (const float*)d_in[12];
        dec_w = (const float*)d_in[13]; dec_b = (const float*)d_in[14];
    }
    const int* src = ei;
    const int* dst = ei + N_EDGES;

    void* p;
    float *h_, *Pd, *Ps, *aggA, *aggB, *t2, *gx, *naccA, *naccB;
    char* wt;
    cudaGetSymbolAddress(&p, g_h);      h_   = (float*)p;
    cudaGetSymbolAddress(&p, g_Pd);     Pd   = (float*)p;
    cudaGetSymbolAddress(&p, g_Ps);     Ps   = (float*)p;
    cudaGetSymbolAddress(&p, g_agg);    aggA = (float*)p;
    cudaGetSymbolAddress(&p, g_agg2);   aggB = (float*)p;
    cudaGetSymbolAddress(&p, g_t2);     t2   = (float*)p;
    cudaGetSymbolAddress(&p, g_x);      gx   = (float*)p;
    cudaGetSymbolAddress(&p, g_naccA);  naccA = (float*)p;
    cudaGetSymbolAddress(&p, g_naccB);  naccB = (float*)p;
    cudaGetSymbolAddress(&p, g_wt);     wt   = (char*)p;
    float* aggs[2]  = {aggA, aggB};
    float* naccs[2] = {naccA, naccB};

    float* out = (float*)d_out;
    float* loss_out;
    float* x_out;
    if (out_size >= N_NODES * DIMX + 1) { loss_out = out; x_out = out + 1; }
    else if (out_size == N_NODES * DIMX) { loss_out = nullptr; x_out = out; }
    else { loss_out = out; x_out = nullptr; }

    cudaFuncSetAttribute(tc_pdps<0>, cudaFuncAttributeMaxDynamicSharedMemorySize, PDPS_SMEM);
    cudaFuncSetAttribute(tc_pdps<1>, cudaFuncAttributeMaxDynamicSharedMemorySize, PDPS_SMEM);
    cudaFuncSetAttribute(tc_edge,    cudaFuncAttributeMaxDynamicSharedMemorySize, EDGE_SMEM);
    cudaFuncSetAttribute(tc_u1u2<0>, cudaFuncAttributeMaxDynamicSharedMemorySize, U1_SMEM);
    cudaFuncSetAttribute(tc_u1u2<1>, cudaFuncAttributeMaxDynamicSharedMemorySize, U1_SMEM);

    // ---- weight prep job table (consumed by fused encoder) ----
    PrepJobs jobs;
    for (int l = 0; l < NLAYERS; ++l) {
        char* lb = wt + (size_t)l * WT_LAYER_STRIDE;
        jobs.src[l*5+0] = m1w + (size_t)l * 256 * 128;            jobs.dst[l*5+0] = lb + WT_W1A; jobs.nelem[l*5+0] = 128*128;
        jobs.src[l*5+1] = m1w + (size_t)l * 256 * 128 + 128*128;  jobs.dst[l*5+1] = lb + WT_W1B; jobs.nelem[l*5+1] = 128*128;
        jobs.src[l*5+2] = m2w + (size_t)l * 128 * 128;            jobs.dst[l*5+2] = lb + WT_W2;  jobs.nelem[l*5+2] = 128*128;
        jobs.src[l*5+3] = u1w + (size_t)l * 256 * 128;            jobs.dst[l*5+3] = lb + WT_U1;  jobs.nelem[l*5+3] = 256*128;
        jobs.src[l*5+4] = u2w + (size_t)l * 128 * 128;            jobs.dst[l*5+4] = lb + WT_U2;  jobs.nelem[l*5+4] = 128*128;
    }

    encoder_kernel<<<(N_NODES * NHID) / 256, 256>>>(X, enc_w, enc_b, h_, jobs);

    for (int l = 0; l < NLAYERS; ++l) {
        char* lb = wt + (size_t)l * WT_LAYER_STRIDE;
        const float* B1  = m1b + l * 128;
        const float* B2  = m2b + l * 128;
        const float* BU1 = u1b + l * 128;
        const float* BU2 = u2b + l * 128;
        const float* Aprev = (l == 0) ? h_ : t2;
        float* aggCur  = aggs[l & 1];
        float* aggNext = aggs[(l + 1) & 1];
        float* accPrev = (l == 0) ? nullptr : naccs[(l - 1) & 1];
        float* accCur  = naccs[l & 1];
        float* zeroAcc = (l == 2) ? accCur : nullptr;

        if (l == 0)
            tc_pdps<0><<<128, 512, PDPS_SMEM>>>(Aprev, lb + WT_W1A, Pd, Ps, nullptr);
        else
            tc_pdps<1><<<128, 512, PDPS_SMEM>>>(Aprev, lb + WT_W1A, Pd, Ps, accPrev);

        tc_edge<<<148, 512, EDGE_SMEM>>>(Pd, Ps, lb + WT_W2, B1, B2, aggCur, dst, src, zeroAcc);

        if (l == 0)
            tc_u1u2<0><<<128, 512, U1_SMEM>>>(Aprev, aggCur, lb + WT_U1, BU1,
                                              lb + WT_U2, BU2, t2, nullptr, accCur, aggNext);
        else
            tc_u1u2<1><<<128, 512, U1_SMEM>>>(Aprev, aggCur, lb + WT_U1, BU1,
                                              lb + WT_U2, BU2, t2, accPrev, accCur, aggNext);
    }

    decoder_kernel<<<(N_NODES * 32) / 256, 256>>>(t2, naccs[(NLAYERS - 1) & 1],
                                                  dec_w, dec_b, gx, x_out);
    disc_kernel<<<dim3(NBATCH, 8), 128>>>(gx, loss_out);
}